// round 10
// baseline (speedup 1.0000x reference)
#include <cuda_runtime.h>
#include <stdint.h>
#include <math.h>

#define N_NODES 10000
#define N_EDGES 320000
#define IN_DIM  512
#define CH      128

#define NB           296        // persistent grid: 2 blocks/SM x 148 SMs, co-resident
#define GEMM_BLOCKS  157
#define EDGE_BLOCKS  64
#define Z2_TASKS     2500       // 4 rows per task
#define GATHER_TASKS 1250       // 8 nodes per task
#define DEC_TASKS    1250       // 8 nodes per task

// ---------------- scratch (device globals; zero-initialized at load) ----------------
__device__ float g_h  [N_NODES * CH];
__device__ float g_xw [N_NODES * CH];
__device__ float g_z1 [N_NODES * CH];
__device__ float g_dinv[N_NODES];
__device__ int   g_cnt [N_NODES];
__device__ int   g_pos [N_NODES];
__device__ int   g_off [N_NODES + 1];
__device__ int   g_src [N_EDGES];
__device__ int   g_tgt [N_EDGES];
__device__ int   g_adj [N_EDGES];
__device__ int   g_eid [N_EDGES];
__device__ float g_sf  [N_EDGES];
__device__ float g_z2c0[N_NODES];

// scheduling state (reset in final phase each run)
__device__ int q_z2, q_gather, q_dec;
__device__ int ct_cvt, ct_g2, ct_fill, ct_gather;
__device__ int flag_scan;
__device__ int bar_ct, bar_gen;     // bar_gen monotonic across replays

#define WS_STRIDE 68
#define SMEM_FLOATS (128 * WS_STRIDE + 64)

// ---------------- tf32 MMA helpers ----------------
__device__ __forceinline__ unsigned f2tf32(float f) {
    unsigned u;
    asm("cvt.rna.tf32.f32 %0, %1;" : "=r"(u) : "f"(f));
    return u;
}

__device__ __forceinline__ void mma_tf32(float c[4], unsigned a0, unsigned a1,
                                         unsigned a2, unsigned a3,
                                         unsigned b0, unsigned b1) {
    asm volatile(
        "mma.sync.aligned.m16n8k8.row.col.f32.tf32.tf32.f32 "
        "{%0,%1,%2,%3}, {%4,%5,%6,%7}, {%8,%9}, {%0,%1,%2,%3};\n"
        : "+f"(c[0]), "+f"(c[1]), "+f"(c[2]), "+f"(c[3])
        : "r"(a0), "r"(a1), "r"(a2), "r"(a3), "r"(b0), "r"(b1));
}

// ---------------- tf32 GEMM block body: out[M,128] = A[M,K] @ W[128,K]^T ----------------
template <int KDIM, bool NORM, bool ROWSCALE>
__device__ __forceinline__ void gemm_tf32_body(
    const float* __restrict__ A, const float* __restrict__ W,
    const float* __restrict__ bias, const float* __restrict__ rs,
    float* __restrict__ out, int M, float scale, int m0, float* smem) {

    const int tid = threadIdx.x, lane = tid & 31, w = tid >> 5;
    const int gid = lane >> 2, tig = lane & 3;
    const int wm = w & 1, wn = w >> 1;
    const int mbase = m0 + wm * 32;
    const int nbase = wn * 32;
    float* Ws = smem;
    float* ssq = smem + 128 * WS_STRIDE;

    float acc[2][4][4];
#pragma unroll
    for (int i = 0; i < 2; i++)
#pragma unroll
        for (int j = 0; j < 4; j++)
#pragma unroll
            for (int q = 0; q < 4; q++) acc[i][j][q] = 0.f;

    bool vlo[2], vhi[2];
    int rlo[2], rhi[2];
#pragma unroll
    for (int i = 0; i < 2; i++) {
        rlo[i] = mbase + i * 16 + gid;
        rhi[i] = rlo[i] + 8;
        vlo[i] = rlo[i] < M;
        vhi[i] = rhi[i] < M;
    }

    for (int kt = 0; kt < KDIM; kt += 64) {
        __syncthreads();
#pragma unroll
        for (int it = 0; it < 8; it++) {
            int idx = tid + it * 256;
            int n = idx >> 4, q = idx & 15;
            float4 v = *(const float4*)(W + (size_t)n * KDIM + kt + q * 4);
            *(float4*)&Ws[n * WS_STRIDE + q * 4] = v;
        }
        __syncthreads();
#pragma unroll
        for (int k8 = 0; k8 < 8; k8++) {
            int kg = kt + k8 * 8;
            unsigned af[2][4];
#pragma unroll
            for (int i = 0; i < 2; i++) {
                const float* Alo = A + (size_t)rlo[i] * KDIM + kg + tig;
                const float* Ahi = A + (size_t)rhi[i] * KDIM + kg + tig;
                float a0 = vlo[i] ? Alo[0] : 0.f;
                float a1 = vhi[i] ? Ahi[0] : 0.f;
                float a2 = vlo[i] ? Alo[4] : 0.f;
                float a3 = vhi[i] ? Ahi[4] : 0.f;
                af[i][0] = f2tf32(a0); af[i][1] = f2tf32(a1);
                af[i][2] = f2tf32(a2); af[i][3] = f2tf32(a3);
            }
#pragma unroll
            for (int j = 0; j < 4; j++) {
                int n = nbase + j * 8 + gid;
                unsigned b0 = f2tf32(Ws[n * WS_STRIDE + k8 * 8 + tig]);
                unsigned b1 = f2tf32(Ws[n * WS_STRIDE + k8 * 8 + tig + 4]);
#pragma unroll
                for (int i = 0; i < 2; i++)
                    mma_tf32(acc[i][j], af[i][0], af[i][1], af[i][2], af[i][3], b0, b1);
            }
        }
    }

    if (bias) {
#pragma unroll
        for (int j = 0; j < 4; j++) {
            int col = nbase + j * 8 + 2 * tig;
            float bv0 = bias[col], bv1 = bias[col + 1];
#pragma unroll
            for (int i = 0; i < 2; i++) {
                acc[i][j][0] += bv0; acc[i][j][1] += bv1;
                acc[i][j][2] += bv0; acc[i][j][3] += bv1;
            }
        }
    }

    float mul_lo[2], mul_hi[2];
#pragma unroll
    for (int i = 0; i < 2; i++) { mul_lo[i] = 1.f; mul_hi[i] = 1.f; }

    if (NORM) {
        __syncthreads();
        if (tid < 64) ssq[tid] = 0.f;
        __syncthreads();
#pragma unroll
        for (int i = 0; i < 2; i++) {
            float plo = 0.f, phi = 0.f;
#pragma unroll
            for (int j = 0; j < 4; j++) {
                plo += acc[i][j][0] * acc[i][j][0] + acc[i][j][1] * acc[i][j][1];
                phi += acc[i][j][2] * acc[i][j][2] + acc[i][j][3] * acc[i][j][3];
            }
            plo += __shfl_xor_sync(0xffffffffu, plo, 1);
            plo += __shfl_xor_sync(0xffffffffu, plo, 2);
            phi += __shfl_xor_sync(0xffffffffu, phi, 1);
            phi += __shfl_xor_sync(0xffffffffu, phi, 2);
            if (tig == 0) {
                atomicAdd(&ssq[wm * 32 + i * 16 + gid], plo);
                atomicAdd(&ssq[wm * 32 + i * 16 + gid + 8], phi);
            }
        }
        __syncthreads();
#pragma unroll
        for (int i = 0; i < 2; i++) {
            mul_lo[i] = scale / fmaxf(sqrtf(ssq[wm * 32 + i * 16 + gid]), 1e-12f);
            mul_hi[i] = scale / fmaxf(sqrtf(ssq[wm * 32 + i * 16 + gid + 8]), 1e-12f);
        }
    }
    if (ROWSCALE) {
#pragma unroll
        for (int i = 0; i < 2; i++) {
            if (vlo[i]) mul_lo[i] *= rs[rlo[i]];
            if (vhi[i]) mul_hi[i] *= rs[rhi[i]];
        }
    }

#pragma unroll
    for (int i = 0; i < 2; i++) {
#pragma unroll
        for (int j = 0; j < 4; j++) {
            int col = nbase + j * 8 + 2 * tig;
            if (vlo[i]) {
                float2 o = make_float2(acc[i][j][0] * mul_lo[i], acc[i][j][1] * mul_lo[i]);
                *(float2*)(out + (size_t)rlo[i] * CH + col) = o;
            }
            if (vhi[i]) {
                float2 o = make_float2(acc[i][j][2] * mul_hi[i], acc[i][j][3] * mul_hi[i]);
                *(float2*)(out + (size_t)rhi[i] * CH + col) = o;
            }
        }
    }
}

// ---------------- z2 body: 4 rows, depth-2 register-pipelined DRAM stream ----------------
__device__ __forceinline__ void z2_body4(const float* __restrict__ x2,
                                         const float* __restrict__ W22,
                                         int row0, float* smem) {
    const int tid = threadIdx.x, lane = tid & 31, wid = tid >> 5;
    const int NV = N_NODES / 4;
    const float4* __restrict__ w0 = (const float4*)W22;
    const float4* __restrict__ w1 = (const float4*)(W22 + N_NODES);
    const float4* xr[4];
#pragma unroll
    for (int k = 0; k < 4; k++)
        xr[k] = (const float4*)(x2 + (size_t)(row0 + k) * N_NODES);

    float s0[4] = {0.f, 0.f, 0.f, 0.f}, s1[4] = {0.f, 0.f, 0.f, 0.f};
    float4 a[4], an[4], an2[4];
#pragma unroll
    for (int k = 0; k < 4; k++) a[k]  = xr[k][tid];
#pragma unroll
    for (int k = 0; k < 4; k++) an[k] = xr[k][256 + tid];

    int j = tid;
#pragma unroll
    for (int c = 0; c < 10; c++) {
        bool v = j < NV;
        int js = v ? j : 0;
        float4 b = w0[js], cc = w1[js];
        if (!v) { b = make_float4(0.f,0.f,0.f,0.f); cc = make_float4(0.f,0.f,0.f,0.f); }
        if (c < 8) {
            int jp = j + 512;
            int jps = (jp < NV) ? jp : 0;
#pragma unroll
            for (int k = 0; k < 4; k++) an2[k] = xr[k][jps];
        }
#pragma unroll
        for (int k = 0; k < 4; k++) {
            s0[k] += a[k].x * b.x  + a[k].y * b.y  + a[k].z * b.z  + a[k].w * b.w;
            s1[k] += a[k].x * cc.x + a[k].y * cc.y + a[k].z * cc.z + a[k].w * cc.w;
        }
#pragma unroll
        for (int k = 0; k < 4; k++) { a[k] = an[k]; an[k] = an2[k]; }
        j += 256;
    }

#pragma unroll
    for (int k = 0; k < 4; k++) {
#pragma unroll
        for (int d = 16; d; d >>= 1) {
            s0[k] += __shfl_xor_sync(0xffffffffu, s0[k], d);
            s1[k] += __shfl_xor_sync(0xffffffffu, s1[k], d);
        }
    }
    float* r0 = smem;
    float* r1 = smem + 32;
    if (lane == 0) {
#pragma unroll
        for (int k = 0; k < 4; k++) { r0[k * 8 + wid] = s0[k]; r1[k * 8 + wid] = s1[k]; }
    }
    __syncthreads();
    if (tid < 4) {
        float y0 = 0.f, y1 = 0.f;
#pragma unroll
        for (int q = 0; q < 8; q++) { y0 += r0[tid * 8 + q]; y1 += r1[tid * 8 + q]; }
        float n = fmaxf(sqrtf(y0 * y0 + y1 * y1), 1e-12f);
        g_z2c0[row0 + tid] = 0.8f * y0 / n;
    }
    __syncthreads();
}

// ---------------- small bodies ----------------
__device__ __forceinline__ bool edges_are_i64(const int* p) {
    bool b = true;
#pragma unroll
    for (int i = 0; i < 8; i++) b = b && (p[2 * i + 1] == 0);
    return b;
}

__device__ __forceinline__ void cvt_count_body(const int* __restrict__ ep, int bb) {
    bool i64 = edges_are_i64(ep);
    for (int e = threadIdx.x + bb * 256; e < N_EDGES; e += EDGE_BLOCKS * 256) {
        int s, t;
        if (i64) {
            const long long* p = (const long long*)ep;
            s = (int)p[e]; t = (int)p[N_EDGES + e];
        } else {
            s = ep[e]; t = ep[N_EDGES + e];
        }
        g_src[e] = s; g_tgt[e] = t;
        atomicAdd(&g_cnt[t], 1);
    }
}

__device__ __forceinline__ void scan_body256(int* wsum) {
    int tid = threadIdx.x, lane = tid & 31, wid = tid >> 5;
    int carry = 0;
    for (int base = 0; base < N_NODES; base += 256) {
        int idx = base + tid;
        int v = (idx < N_NODES) ? g_cnt[idx] : 0;
        int x = v;
#pragma unroll
        for (int d = 1; d < 32; d <<= 1) {
            int y = __shfl_up_sync(0xffffffffu, x, d);
            if (lane >= d) x += y;
        }
        if (lane == 31) wsum[wid] = x;
        __syncthreads();
        if (wid == 0 && lane < 8) {
            int s = wsum[lane];
#pragma unroll
            for (int d = 1; d < 8; d <<= 1) {
                int y = __shfl_up_sync(0xffu, s, d);
                if (lane >= d) s += y;
            }
            wsum[lane] = s;
        }
        __syncthreads();
        int offset = wid ? wsum[wid - 1] : 0;
        if (idx < N_NODES) {
            g_off[idx] = carry + offset + x - v;
            g_dinv[idx] = rsqrtf((float)(v + 1));
        }
        carry += wsum[7];
        __syncthreads();
    }
    if (tid == 0) g_off[N_NODES] = carry;
}

__device__ __forceinline__ void fill_body(int bb) {
    for (int e = threadIdx.x + bb * 256; e < N_EDGES; e += EDGE_BLOCKS * 256) {
        int t = g_tgt[e];
        int p = atomicAdd(&g_pos[t], 1);
        int w = g_off[t] + p;
        g_adj[w] = g_src[e];
        g_eid[w] = e;
    }
}

__device__ __forceinline__ void gather_body(const float* __restrict__ bg,
                                            int i, int c) {
    float di = g_dinv[i];
    float acc = g_xw[i * CH + c];
    int s0 = g_off[i], s1 = g_off[i + 1];
    int j = s0;
    for (; j + 4 <= s1; j += 4) {
        int a0 = g_adj[j], a1 = g_adj[j + 1], a2 = g_adj[j + 2], a3 = g_adj[j + 3];
        float v0 = g_xw[a0 * CH + c], v1 = g_xw[a1 * CH + c];
        float v2 = g_xw[a2 * CH + c], v3 = g_xw[a3 * CH + c];
        acc += (v0 + v1) + (v2 + v3);
    }
    for (; j < s1; j++) acc += g_xw[g_adj[j] * CH + c];
    g_z1[i * CH + c] = acc * di + bg[c];
}

// ---------------- the persistent mega kernel ----------------
__global__ void __launch_bounds__(256, 2) mega_kernel(
    const float* __restrict__ x,  const float* __restrict__ W2,
    const float* __restrict__ b2, const float* __restrict__ Wg,
    const float* __restrict__ bg, const float* __restrict__ W22,
    const int* __restrict__ edge, const float* __restrict__ x2,
    float* __restrict__ out) {

    __shared__ float smem[SMEM_FLOATS];
    __shared__ int s_w, s_t, s_last, s_wsum[8];
    const int b = blockIdx.x, tid = threadIdx.x;

    // ================= fixed roles =================
    if (b < GEMM_BLOCKS) {
        // gemm1: h = normalize(x @ W2^T + b2) * 1.8   (tile b)
        gemm_tf32_body<IN_DIM, true, false>(x, W2, b2, nullptr, g_h,
                                            N_NODES, 1.8f, b * 64, smem);
        // wait for scan (dinv), helping z2
        bool oZ = false;
        while (true) {
            __syncthreads();
            if (tid == 0) {
                s_w = atomicAdd(&flag_scan, 0);
                s_t = (!s_w && !oZ) ? atomicAdd(&q_z2, 1) : Z2_TASKS;
            }
            __syncthreads();
            if (s_w) break;
            int t = s_t;
            if (t < Z2_TASKS) z2_body4(x2, W22, t * 4, smem);
            else { oZ = true; __nanosleep(256); }
        }
        __threadfence();
        // gemm2: xw = (h @ Wg^T) * dinv[row]  (same tile -> g_h rows already ours)
        gemm_tf32_body<CH, false, true>(g_h, Wg, nullptr, g_dinv, g_xw,
                                        N_NODES, 1.0f, b * 64, smem);
        __threadfence();
        __syncthreads();
        if (tid == 0) atomicAdd(&ct_g2, 1);
    } else if (b < GEMM_BLOCKS + EDGE_BLOCKS) {
        int bb = b - GEMM_BLOCKS;
        cvt_count_body(edge, bb);
        __threadfence();
        __syncthreads();
        if (tid == 0) s_last = (atomicAdd(&ct_cvt, 1) == EDGE_BLOCKS - 1);
        __syncthreads();
        if (s_last) {
            __threadfence();
            scan_body256(s_wsum);
            __threadfence();
            __syncthreads();
            if (tid == 0) atomicExch(&flag_scan, 1);
        } else {
            bool oZ = false;
            while (true) {
                __syncthreads();
                if (tid == 0) {
                    s_w = atomicAdd(&flag_scan, 0);
                    s_t = (!s_w && !oZ) ? atomicAdd(&q_z2, 1) : Z2_TASKS;
                }
                __syncthreads();
                if (s_w) break;
                int t = s_t;
                if (t < Z2_TASKS) z2_body4(x2, W22, t * 4, smem);
                else { oZ = true; __nanosleep(256); }
            }
        }
        __threadfence();
        fill_body(bb);
        __threadfence();
        __syncthreads();
        if (tid == 0) atomicAdd(&ct_fill, 1);
    }

    // ================= main work loop (all blocks) =================
    {
        bool gG = false, gD = false, oG = false, oD = false, oZ = false; // tid0 state
        while (true) {
            __syncthreads();
            if (tid == 0) {
                int w = 4, t = -1;
                if (!gG) gG = (atomicAdd(&ct_g2, 0) == GEMM_BLOCKS) &&
                              (atomicAdd(&ct_fill, 0) == EDGE_BLOCKS);
                if (gG && !oG) {
                    t = atomicAdd(&q_gather, 1);
                    if (t < GATHER_TASKS) w = 1; else oG = true;
                }
                if (w == 4 && oG) {
                    if (!gD) gD = (atomicAdd(&ct_gather, 0) == GATHER_TASKS);
                    if (gD && !oD) {
                        t = atomicAdd(&q_dec, 1);
                        if (t < DEC_TASKS) w = 2; else oD = true;
                    }
                }
                if (w == 4 && !oZ) {
                    t = atomicAdd(&q_z2, 1);
                    if (t < Z2_TASKS) w = 3; else oZ = true;
                }
                if (w == 4 && oZ && oG && oD) w = 0;
                s_w = w; s_t = t;
            }
            __syncthreads();
            int w = s_w, t = s_t;
            if (w == 0) break;
            if (w == 1) {
                __threadfence();
#pragma unroll
                for (int it = 0; it < 4; it++) {
                    int node = t * 8 + it * 2 + (tid >> 7);
                    if (node < N_NODES) gather_body(bg, node, tid & 127);
                }
                __threadfence();
                __syncthreads();
                if (tid == 0) atomicAdd(&ct_gather, 1);
            } else if (w == 2) {
                __threadfence();
                int lane = tid & 31;
                int node = t * 8 + (tid >> 5);
                if (node < N_NODES) {
                    float4 zc = *(const float4*)(g_z1 + (size_t)node * CH + lane * 4);
                    int e0 = g_off[node], e1 = g_off[node + 1];
                    for (int j = e0; j < e1; j++) {
                        int s = g_adj[j];
                        const float4 a = *(const float4*)(g_z1 + (size_t)s * CH + lane * 4);
                        float d = a.x * zc.x + a.y * zc.y + a.z * zc.z + a.w * zc.w;
#pragma unroll
                        for (int o = 16; o; o >>= 1) d += __shfl_xor_sync(0xffffffffu, d, o);
                        if (lane == 0) g_sf[g_eid[j]] = 1.f / (1.f + __expf(-d));
                    }
                }
            } else if (w == 3) {
                z2_body4(x2, W22, t * 4, smem);
            } else {
                __nanosleep(300);
            }
        }
    }

    // ================= global barrier (all NB blocks co-resident) =================
    __threadfence();
    __syncthreads();
    if (tid == 0) {
        int g = atomicAdd(&bar_gen, 0);
        if (atomicAdd(&bar_ct, 1) == NB - 1) {
            atomicExch(&bar_ct, 0);
            __threadfence();
            atomicAdd(&bar_gen, 1);
        } else {
            while (atomicAdd(&bar_gen, 0) == g) __nanosleep(200);
        }
    }
    __syncthreads();
    __threadfence();

    // ================= final combine + full state reset =================
    for (int e = b * 256 + tid; e < N_EDGES; e += NB * 256) {
        float sf = g_sf[e];
        float vn = g_z2c0[g_src[e]] + g_z2c0[g_tgt[e]];
        float sn = 1.f / (1.f + __expf(-vn));
        out[e] = sf * sf + (1.f - sf) * sn;
    }
    for (int i = b * 256 + tid; i < N_NODES; i += NB * 256) {
        g_cnt[i] = 0; g_pos[i] = 0;
    }
    if (b == 0 && tid == 0) {
        q_z2 = 0; q_gather = 0; q_dec = 0;
        ct_cvt = 0; ct_g2 = 0; ct_fill = 0; ct_gather = 0;
        flag_scan = 0;
    }
}

// ---------------- launch ----------------
extern "C" void kernel_launch(void* const* d_in, const int* in_sizes, int n_in,
                              void* d_out, int out_size) {
    const float* x    = (const float*)d_in[0];
    const float* x2   = (const float*)d_in[1];
    const float* W2   = (const float*)d_in[2];
    const float* b2   = (const float*)d_in[3];
    const float* Wg   = (const float*)d_in[4];
    const float* bg   = (const float*)d_in[5];
    const float* W22  = (const float*)d_in[6];
    const int*   edge = (const int*)d_in[7];
    float* out = (float*)d_out;

    mega_kernel<<<NB, 256>>>(x, W2, b2, Wg, bg, W22, edge, x2, out);
}

// round 11
// speedup vs baseline: 1.2881x; 1.2881x over previous
#include <cuda_runtime.h>
#include <stdint.h>
#include <math.h>

#define N_NODES 10000
#define N_EDGES 320000
#define IN_DIM  512
#define CH      128

// ---------------- scratch (device globals; zero-initialized at load) ----------------
__device__ float g_h  [N_NODES * CH];
__device__ float g_xw [N_NODES * CH];
__device__ float g_z1 [N_NODES * CH];
__device__ float g_dinv[N_NODES];
__device__ int   g_cnt [N_NODES];       // re-zeroed by decoder each run
__device__ int   g_pos [N_NODES];       // re-zeroed by decoder each run
__device__ int   g_off [N_NODES + 1];
__device__ int   g_src [N_EDGES];
__device__ int   g_tgt [N_EDGES];
__device__ int   g_adj [N_EDGES];
__device__ int   g_eid [N_EDGES];
__device__ float g_z2c0[N_NODES];

// z2: 4 rows per block; static slices (dynamic queues measured slower, R9)
#define Z2A_BLK 900    // rows [0, 3600)
#define Z2B_BLK 875    // rows [3600, 7100)
#define Z2C_BLK 725    // rows [7100, 10000)

#define GEMM_BLOCKS 157
#define AUX_BLOCKS  64          // cvt_count role (fatA) / fill role (fatB)

// ---------------- edge conversion (role inside fatA) ----------------
__device__ __forceinline__ bool edges_are_i64(const int* p) {
    bool b = true;
#pragma unroll
    for (int i = 0; i < 8; i++) b = b && (p[2 * i + 1] == 0);
    return b;
}

__device__ __forceinline__ void cvt_count_body(const int* __restrict__ ep, int bb) {
    bool i64 = edges_are_i64(ep);
    for (int e = threadIdx.x + bb * 256; e < N_EDGES; e += AUX_BLOCKS * 256) {
        int s, t;
        if (i64) {
            const long long* p = (const long long*)ep;
            s = (int)p[e]; t = (int)p[N_EDGES + e];
        } else {
            s = ep[e]; t = ep[N_EDGES + e];
        }
        g_src[e] = s; g_tgt[e] = t;
        atomicAdd(&g_cnt[t], 1);
    }
}

// ---------------- scan: exclusive prefix of cnt -> off, dinv = rsqrt(cnt+1) ----------------
__global__ void scan_kernel() {
    __shared__ int wsum[32];
    int tid = threadIdx.x, lane = tid & 31, wid = tid >> 5;
    int carry = 0;
    for (int base = 0; base < N_NODES; base += 1024) {
        int idx = base + tid;
        int v = (idx < N_NODES) ? g_cnt[idx] : 0;
        int x = v;
#pragma unroll
        for (int d = 1; d < 32; d <<= 1) {
            int y = __shfl_up_sync(0xffffffffu, x, d);
            if (lane >= d) x += y;
        }
        if (lane == 31) wsum[wid] = x;
        __syncthreads();
        if (wid == 0) {
            int s = wsum[lane];
#pragma unroll
            for (int d = 1; d < 32; d <<= 1) {
                int y = __shfl_up_sync(0xffffffffu, s, d);
                if (lane >= d) s += y;
            }
            wsum[lane] = s;
        }
        __syncthreads();
        int offset = wid ? wsum[wid - 1] : 0;
        if (idx < N_NODES) {
            g_off[idx] = carry + offset + x - v;
            g_dinv[idx] = rsqrtf((float)(v + 1));
        }
        carry += wsum[31];
        __syncthreads();
    }
    if (tid == 0) g_off[N_NODES] = carry;
}

// ---------------- tf32 MMA helpers ----------------
__device__ __forceinline__ unsigned f2tf32(float f) {
    unsigned u;
    asm("cvt.rna.tf32.f32 %0, %1;" : "=r"(u) : "f"(f));
    return u;
}

__device__ __forceinline__ void mma_tf32(float c[4], unsigned a0, unsigned a1,
                                         unsigned a2, unsigned a3,
                                         unsigned b0, unsigned b1) {
    asm volatile(
        "mma.sync.aligned.m16n8k8.row.col.f32.tf32.tf32.f32 "
        "{%0,%1,%2,%3}, {%4,%5,%6,%7}, {%8,%9}, {%0,%1,%2,%3};\n"
        : "+f"(c[0]), "+f"(c[1]), "+f"(c[2]), "+f"(c[3])
        : "r"(a0), "r"(a1), "r"(a2), "r"(a3), "r"(b0), "r"(b1));
}

#define WS_STRIDE 68
#define SMEM_FLOATS (128 * WS_STRIDE + 64)

// ---------------- tf32 GEMM block body: out[M,128] = A[M,K] @ W[128,K]^T ----------------
template <int KDIM, bool NORM, bool ROWSCALE>
__device__ __forceinline__ void gemm_tf32_body(
    const float* __restrict__ A, const float* __restrict__ W,
    const float* __restrict__ bias, const float* __restrict__ rs,
    float* __restrict__ out, int M, float scale, int m0, float* smem) {

    const int tid = threadIdx.x, lane = tid & 31, w = tid >> 5;
    const int gid = lane >> 2, tig = lane & 3;
    const int wm = w & 1, wn = w >> 1;
    const int mbase = m0 + wm * 32;
    const int nbase = wn * 32;
    float* Ws = smem;
    float* ssq = smem + 128 * WS_STRIDE;

    float acc[2][4][4];
#pragma unroll
    for (int i = 0; i < 2; i++)
#pragma unroll
        for (int j = 0; j < 4; j++)
#pragma unroll
            for (int q = 0; q < 4; q++) acc[i][j][q] = 0.f;

    bool vlo[2], vhi[2];
    int rlo[2], rhi[2];
#pragma unroll
    for (int i = 0; i < 2; i++) {
        rlo[i] = mbase + i * 16 + gid;
        rhi[i] = rlo[i] + 8;
        vlo[i] = rlo[i] < M;
        vhi[i] = rhi[i] < M;
    }

    for (int kt = 0; kt < KDIM; kt += 64) {
        __syncthreads();
#pragma unroll
        for (int it = 0; it < 8; it++) {
            int idx = tid + it * 256;
            int n = idx >> 4, q = idx & 15;
            float4 v = *(const float4*)(W + (size_t)n * KDIM + kt + q * 4);
            *(float4*)&Ws[n * WS_STRIDE + q * 4] = v;
        }
        __syncthreads();
#pragma unroll
        for (int k8 = 0; k8 < 8; k8++) {
            int kg = kt + k8 * 8;
            unsigned af[2][4];
#pragma unroll
            for (int i = 0; i < 2; i++) {
                const float* Alo = A + (size_t)rlo[i] * KDIM + kg + tig;
                const float* Ahi = A + (size_t)rhi[i] * KDIM + kg + tig;
                float a0 = vlo[i] ? Alo[0] : 0.f;
                float a1 = vhi[i] ? Ahi[0] : 0.f;
                float a2 = vlo[i] ? Alo[4] : 0.f;
                float a3 = vhi[i] ? Ahi[4] : 0.f;
                af[i][0] = f2tf32(a0); af[i][1] = f2tf32(a1);
                af[i][2] = f2tf32(a2); af[i][3] = f2tf32(a3);
            }
#pragma unroll
            for (int j = 0; j < 4; j++) {
                int n = nbase + j * 8 + gid;
                unsigned b0 = f2tf32(Ws[n * WS_STRIDE + k8 * 8 + tig]);
                unsigned b1 = f2tf32(Ws[n * WS_STRIDE + k8 * 8 + tig + 4]);
#pragma unroll
                for (int i = 0; i < 2; i++)
                    mma_tf32(acc[i][j], af[i][0], af[i][1], af[i][2], af[i][3], b0, b1);
            }
        }
    }

    if (bias) {
#pragma unroll
        for (int j = 0; j < 4; j++) {
            int col = nbase + j * 8 + 2 * tig;
            float bv0 = bias[col], bv1 = bias[col + 1];
#pragma unroll
            for (int i = 0; i < 2; i++) {
                acc[i][j][0] += bv0; acc[i][j][1] += bv1;
                acc[i][j][2] += bv0; acc[i][j][3] += bv1;
            }
        }
    }

    float mul_lo[2], mul_hi[2];
#pragma unroll
    for (int i = 0; i < 2; i++) { mul_lo[i] = 1.f; mul_hi[i] = 1.f; }

    if (NORM) {
        __syncthreads();
        if (tid < 64) ssq[tid] = 0.f;
        __syncthreads();
#pragma unroll
        for (int i = 0; i < 2; i++) {
            float plo = 0.f, phi = 0.f;
#pragma unroll
            for (int j = 0; j < 4; j++) {
                plo += acc[i][j][0] * acc[i][j][0] + acc[i][j][1] * acc[i][j][1];
                phi += acc[i][j][2] * acc[i][j][2] + acc[i][j][3] * acc[i][j][3];
            }
            plo += __shfl_xor_sync(0xffffffffu, plo, 1);
            plo += __shfl_xor_sync(0xffffffffu, plo, 2);
            phi += __shfl_xor_sync(0xffffffffu, phi, 1);
            phi += __shfl_xor_sync(0xffffffffu, phi, 2);
            if (tig == 0) {
                atomicAdd(&ssq[wm * 32 + i * 16 + gid], plo);
                atomicAdd(&ssq[wm * 32 + i * 16 + gid + 8], phi);
            }
        }
        __syncthreads();
#pragma unroll
        for (int i = 0; i < 2; i++) {
            mul_lo[i] = scale / fmaxf(sqrtf(ssq[wm * 32 + i * 16 + gid]), 1e-12f);
            mul_hi[i] = scale / fmaxf(sqrtf(ssq[wm * 32 + i * 16 + gid + 8]), 1e-12f);
        }
    }
    if (ROWSCALE) {
#pragma unroll
        for (int i = 0; i < 2; i++) {
            if (vlo[i]) mul_lo[i] *= rs[rlo[i]];
            if (vhi[i]) mul_hi[i] *= rs[rhi[i]];
        }
    }

#pragma unroll
    for (int i = 0; i < 2; i++) {
#pragma unroll
        for (int j = 0; j < 4; j++) {
            int col = nbase + j * 8 + 2 * tig;
            if (vlo[i]) {
                float2 o = make_float2(acc[i][j][0] * mul_lo[i], acc[i][j][1] * mul_lo[i]);
                *(float2*)(out + (size_t)rlo[i] * CH + col) = o;
            }
            if (vhi[i]) {
                float2 o = make_float2(acc[i][j][2] * mul_hi[i], acc[i][j][3] * mul_hi[i]);
                *(float2*)(out + (size_t)rhi[i] * CH + col) = o;
            }
        }
    }
}

// ---------------- z2 body: 4 rows per block, depth-2 register-pipelined DRAM stream ----------------
__device__ __forceinline__ void z2_body4(const float* __restrict__ x2,
                                         const float* __restrict__ W22,
                                         int row0, float* smem) {
    const int tid = threadIdx.x, lane = tid & 31, wid = tid >> 5;
    const int NV = N_NODES / 4;   // 2500 float4 per row; 10 chunks of 256
    const float4* __restrict__ w0 = (const float4*)W22;
    const float4* __restrict__ w1 = (const float4*)(W22 + N_NODES);
    const float4* xr[4];
#pragma unroll
    for (int k = 0; k < 4; k++)
        xr[k] = (const float4*)(x2 + (size_t)(row0 + k) * N_NODES);

    float s0[4] = {0.f, 0.f, 0.f, 0.f}, s1[4] = {0.f, 0.f, 0.f, 0.f};
    float4 a[4], an[4], an2[4];

#pragma unroll
    for (int k = 0; k < 4; k++) a[k]  = xr[k][tid];
#pragma unroll
    for (int k = 0; k < 4; k++) an[k] = xr[k][256 + tid];

    int j = tid;
#pragma unroll
    for (int c = 0; c < 10; c++) {
        bool v = j < NV;
        int js = v ? j : 0;
        float4 b = w0[js], cc = w1[js];
        if (!v) { b = make_float4(0.f,0.f,0.f,0.f); cc = make_float4(0.f,0.f,0.f,0.f); }
        if (c < 8) {
            int jp = j + 512;
            int jps = (jp < NV) ? jp : 0;
#pragma unroll
            for (int k = 0; k < 4; k++) an2[k] = xr[k][jps];
        }
#pragma unroll
        for (int k = 0; k < 4; k++) {
            s0[k] += a[k].x * b.x  + a[k].y * b.y  + a[k].z * b.z  + a[k].w * b.w;
            s1[k] += a[k].x * cc.x + a[k].y * cc.y + a[k].z * cc.z + a[k].w * cc.w;
        }
#pragma unroll
        for (int k = 0; k < 4; k++) { a[k] = an[k]; an[k] = an2[k]; }
        j += 256;
    }

#pragma unroll
    for (int k = 0; k < 4; k++) {
#pragma unroll
        for (int d = 16; d; d >>= 1) {
            s0[k] += __shfl_xor_sync(0xffffffffu, s0[k], d);
            s1[k] += __shfl_xor_sync(0xffffffffu, s1[k], d);
        }
    }
    float* r0 = smem;        // [4][8]
    float* r1 = smem + 32;   // [4][8]
    if (lane == 0) {
#pragma unroll
        for (int k = 0; k < 4; k++) { r0[k * 8 + wid] = s0[k]; r1[k * 8 + wid] = s1[k]; }
    }
    __syncthreads();
    if (tid < 4) {
        float y0 = 0.f, y1 = 0.f;
#pragma unroll
        for (int q = 0; q < 8; q++) { y0 += r0[tid * 8 + q]; y1 += r1[tid * 8 + q]; }
        float n = fmaxf(sqrtf(y0 * y0 + y1 * y1), 1e-12f);
        g_z2c0[row0 + tid] = 0.8f * y0 / n;
    }
}

// ---------------- fatA: gemm1 + cvt_count + z2 rows [0, 3600) ----------------
__global__ __launch_bounds__(256) void fatA_kernel(
    const float* __restrict__ x, const float* __restrict__ W2,
    const float* __restrict__ b2, const int* __restrict__ edge,
    const float* __restrict__ x2, const float* __restrict__ W22) {
    __shared__ float smem[SMEM_FLOATS];
    int b = blockIdx.x;
    if (b < GEMM_BLOCKS) {
        gemm_tf32_body<IN_DIM, true, false>(x, W2, b2, nullptr, g_h,
                                            N_NODES, 1.8f, b * 64, smem);
    } else if (b < GEMM_BLOCKS + AUX_BLOCKS) {
        cvt_count_body(edge, b - GEMM_BLOCKS);
    } else {
        z2_body4(x2, W22, (b - GEMM_BLOCKS - AUX_BLOCKS) * 4, smem);
    }
}

// ---------------- fatB: gemm2 + CSR fill + z2 rows [3600, 7100) ----------------
__global__ __launch_bounds__(256) void fatB_kernel(
    const float* __restrict__ Wg,
    const float* __restrict__ x2, const float* __restrict__ W22) {
    __shared__ float smem[SMEM_FLOATS];
    int b = blockIdx.x;
    if (b < GEMM_BLOCKS) {
        gemm_tf32_body<CH, false, true>(g_h, Wg, nullptr, g_dinv, g_xw,
                                        N_NODES, 1.0f, b * 64, smem);
    } else if (b < GEMM_BLOCKS + AUX_BLOCKS) {
        int bb = b - GEMM_BLOCKS;
        for (int e = threadIdx.x + bb * 256; e < N_EDGES; e += AUX_BLOCKS * 256) {
            int t = g_tgt[e];
            int p = atomicAdd(&g_pos[t], 1);
            int w = g_off[t] + p;
            g_adj[w] = g_src[e];
            g_eid[w] = e;
        }
    } else {
        z2_body4(x2, W22, 3600 + (b - GEMM_BLOCKS - AUX_BLOCKS) * 4, smem);
    }
}

// ---------------- gather body ----------------
__device__ __forceinline__ void gather_body(const float* __restrict__ bg,
                                            int i, int c) {
    float di = g_dinv[i];
    float acc = g_xw[i * CH + c];
    int s0 = g_off[i], s1 = g_off[i + 1];
    int j = s0;
    for (; j + 4 <= s1; j += 4) {
        int a0 = g_adj[j], a1 = g_adj[j + 1], a2 = g_adj[j + 2], a3 = g_adj[j + 3];
        float v0 = g_xw[a0 * CH + c], v1 = g_xw[a1 * CH + c];
        float v2 = g_xw[a2 * CH + c], v3 = g_xw[a3 * CH + c];
        acc += (v0 + v1) + (v2 + v3);
    }
    for (; j < s1; j++) acc += g_xw[g_adj[j] * CH + c];
    g_z1[i * CH + c] = acc * di + bg[c];
}

// ---------------- fatC: z2 rows [7100, 10000) + gather ----------------
#define GATHER_BLOCKS 5000
__global__ __launch_bounds__(256) void fatC_kernel(
    const float* __restrict__ bg,
    const float* __restrict__ x2, const float* __restrict__ W22) {
    __shared__ float smem[SMEM_FLOATS];
    int b = blockIdx.x;
    if (b < Z2C_BLK) {
        z2_body4(x2, W22, 7100 + b * 4, smem);
    } else {
        int g = b - Z2C_BLK;
        int node = g * 2 + (threadIdx.x >> 7);
        gather_body(bg, node, threadIdx.x & 127);
    }
}

// ---------------- decoder: warp per target node, CSR order, 4-edge unroll ----------------
__global__ __launch_bounds__(256) void decoder_kernel(float* __restrict__ out) {
    int gtid = blockIdx.x * blockDim.x + threadIdx.x;
    if (gtid < N_NODES) { g_cnt[gtid] = 0; g_pos[gtid] = 0; }

    int node = gtid >> 5;
    int lane = threadIdx.x & 31;
    if (node >= N_NODES) return;
    float4 zc = *(const float4*)(g_z1 + (size_t)node * CH + lane * 4);
    float zc0 = g_z2c0[node];
    int s0 = g_off[node], s1 = g_off[node + 1];
    int j = s0;
    // 4 edges per iteration: interleaves 4 independent shfl-reduction chains
    for (; j + 4 <= s1; j += 4) {
        int sn[4]; float d[4];
#pragma unroll
        for (int k = 0; k < 4; k++) sn[k] = g_adj[j + k];
#pragma unroll
        for (int k = 0; k < 4; k++) {
            const float4 a = *(const float4*)(g_z1 + (size_t)sn[k] * CH + lane * 4);
            d[k] = a.x * zc.x + a.y * zc.y + a.z * zc.z + a.w * zc.w;
        }
#pragma unroll
        for (int o = 16; o; o >>= 1) {
#pragma unroll
            for (int k = 0; k < 4; k++)
                d[k] += __shfl_xor_sync(0xffffffffu, d[k], o);
        }
        if (lane == 0) {
#pragma unroll
            for (int k = 0; k < 4; k++) {
                float vn = g_z2c0[sn[k]] + zc0;
                float sf = 1.f / (1.f + __expf(-d[k]));
                float sg = 1.f / (1.f + __expf(-vn));
                out[g_eid[j + k]] = sf * sf + (1.f - sf) * sg;
            }
        }
    }
    for (; j < s1; j++) {
        int s = g_adj[j];
        const float4 a = *(const float4*)(g_z1 + (size_t)s * CH + lane * 4);
        float d = a.x * zc.x + a.y * zc.y + a.z * zc.z + a.w * zc.w;
#pragma unroll
        for (int o = 16; o; o >>= 1) d += __shfl_xor_sync(0xffffffffu, d, o);
        if (lane == 0) {
            float vn = g_z2c0[s] + zc0;
            float sf = 1.f / (1.f + __expf(-d));
            float sg = 1.f / (1.f + __expf(-vn));
            out[g_eid[j]] = sf * sf + (1.f - sf) * sg;
        }
    }
}

// ---------------- launch ----------------
extern "C" void kernel_launch(void* const* d_in, const int* in_sizes, int n_in,
                              void* d_out, int out_size) {
    const float* x    = (const float*)d_in[0];
    const float* x2   = (const float*)d_in[1];
    const float* W2   = (const float*)d_in[2];
    const float* b2   = (const float*)d_in[3];
    const float* Wg   = (const float*)d_in[4];
    const float* bg   = (const float*)d_in[5];
    const float* W22  = (const float*)d_in[6];
    const int*   edge = (const int*)d_in[7];
    float* out = (float*)d_out;

    fatA_kernel<<<GEMM_BLOCKS + AUX_BLOCKS + Z2A_BLK, 256>>>(x, W2, b2, edge, x2, W22);
    scan_kernel<<<1, 1024>>>();
    fatB_kernel<<<GEMM_BLOCKS + AUX_BLOCKS + Z2B_BLK, 256>>>(Wg, x2, W22);
    fatC_kernel<<<Z2C_BLK + GATHER_BLOCKS, 256>>>(bg, x2, W22);
    decoder_kernel<<<(N_NODES * 32 + 255) / 256, 256>>>(out);
}

// round 12
// speedup vs baseline: 1.3450x; 1.0442x over previous
#include <cuda_runtime.h>
#include <stdint.h>
#include <math.h>

#define N_NODES 10000
#define N_EDGES 320000
#define IN_DIM  512
#define CH      128

// ---------------- scratch (device globals; zero-initialized at load) ----------------
__device__ float g_h  [N_NODES * CH];
__device__ float g_xw [N_NODES * CH];
__device__ float g_z1 [N_NODES * CH];
__device__ float g_dinv[N_NODES];
__device__ int   g_cnt [N_NODES];       // re-zeroed by decoder each run
__device__ int   g_pos [N_NODES];       // re-zeroed by decoder each run
__device__ int   g_off [N_NODES + 1];
__device__ int   g_src [N_EDGES];
__device__ int   g_tgt [N_EDGES];
__device__ int   g_adj [N_EDGES];
__device__ int   g_eid [N_EDGES];
__device__ float g_z2c0[N_NODES];

// z2: 4 rows per block; static slices
#define Z2A_BLK 825    // rows [0, 3300)
#define Z2B_BLK 875    // rows [3300, 6800)
#define Z2C_BLK 800    // rows [6800, 10000)

#define GEMM_BLOCKS 157
#define AUX_BLOCKS  64          // cvt_count role (fatA) / fill role (fatB)

// ---------------- edge conversion (role inside fatA) ----------------
__device__ __forceinline__ bool edges_are_i64(const int* p) {
    bool b = true;
#pragma unroll
    for (int i = 0; i < 8; i++) b = b && (p[2 * i + 1] == 0);
    return b;
}

__device__ __forceinline__ void cvt_count_body(const int* __restrict__ ep, int bb) {
    bool i64 = edges_are_i64(ep);
    for (int e = threadIdx.x + bb * 256; e < N_EDGES; e += AUX_BLOCKS * 256) {
        int s, t;
        if (i64) {
            const long long* p = (const long long*)ep;
            s = (int)p[e]; t = (int)p[N_EDGES + e];
        } else {
            s = ep[e]; t = ep[N_EDGES + e];
        }
        g_src[e] = s; g_tgt[e] = t;
        atomicAdd(&g_cnt[t], 1);
    }
}

// ---------------- scan: exclusive prefix of cnt -> off, dinv = rsqrt(cnt+1) ----------------
__global__ void scan_kernel() {
    __shared__ int wsum[32];
    int tid = threadIdx.x, lane = tid & 31, wid = tid >> 5;
    int carry = 0;
    for (int base = 0; base < N_NODES; base += 1024) {
        int idx = base + tid;
        int v = (idx < N_NODES) ? g_cnt[idx] : 0;
        int x = v;
#pragma unroll
        for (int d = 1; d < 32; d <<= 1) {
            int y = __shfl_up_sync(0xffffffffu, x, d);
            if (lane >= d) x += y;
        }
        if (lane == 31) wsum[wid] = x;
        __syncthreads();
        if (wid == 0) {
            int s = wsum[lane];
#pragma unroll
            for (int d = 1; d < 32; d <<= 1) {
                int y = __shfl_up_sync(0xffffffffu, s, d);
                if (lane >= d) s += y;
            }
            wsum[lane] = s;
        }
        __syncthreads();
        int offset = wid ? wsum[wid - 1] : 0;
        if (idx < N_NODES) {
            g_off[idx] = carry + offset + x - v;
            g_dinv[idx] = rsqrtf((float)(v + 1));
        }
        carry += wsum[31];
        __syncthreads();
    }
    if (tid == 0) g_off[N_NODES] = carry;
}

// ---------------- tf32 MMA helpers ----------------
__device__ __forceinline__ unsigned f2tf32(float f) {
    unsigned u;
    asm("cvt.rna.tf32.f32 %0, %1;" : "=r"(u) : "f"(f));
    return u;
}

__device__ __forceinline__ void mma_tf32(float c[4], unsigned a0, unsigned a1,
                                         unsigned a2, unsigned a3,
                                         unsigned b0, unsigned b1) {
    asm volatile(
        "mma.sync.aligned.m16n8k8.row.col.f32.tf32.tf32.f32 "
        "{%0,%1,%2,%3}, {%4,%5,%6,%7}, {%8,%9}, {%0,%1,%2,%3};\n"
        : "+f"(c[0]), "+f"(c[1]), "+f"(c[2]), "+f"(c[3])
        : "r"(a0), "r"(a1), "r"(a2), "r"(a3), "r"(b0), "r"(b1));
}

#define WS_STRIDE 68
#define SMEM_FLOATS (128 * WS_STRIDE + 64)

// ---------------- tf32 GEMM block body: out[M,128] = A[M,K] @ W[128,K]^T ----------------
template <int KDIM, bool NORM, bool ROWSCALE>
__device__ __forceinline__ void gemm_tf32_body(
    const float* __restrict__ A, const float* __restrict__ W,
    const float* __restrict__ bias, const float* __restrict__ rs,
    float* __restrict__ out, int M, float scale, int m0, float* smem) {

    const int tid = threadIdx.x, lane = tid & 31, w = tid >> 5;
    const int gid = lane >> 2, tig = lane & 3;
    const int wm = w & 1, wn = w >> 1;
    const int mbase = m0 + wm * 32;
    const int nbase = wn * 32;
    float* Ws = smem;
    float* ssq = smem + 128 * WS_STRIDE;

    float acc[2][4][4];
#pragma unroll
    for (int i = 0; i < 2; i++)
#pragma unroll
        for (int j = 0; j < 4; j++)
#pragma unroll
            for (int q = 0; q < 4; q++) acc[i][j][q] = 0.f;

    bool vlo[2], vhi[2];
    int rlo[2], rhi[2];
#pragma unroll
    for (int i = 0; i < 2; i++) {
        rlo[i] = mbase + i * 16 + gid;
        rhi[i] = rlo[i] + 8;
        vlo[i] = rlo[i] < M;
        vhi[i] = rhi[i] < M;
    }

    for (int kt = 0; kt < KDIM; kt += 64) {
        __syncthreads();
#pragma unroll
        for (int it = 0; it < 8; it++) {
            int idx = tid + it * 256;
            int n = idx >> 4, q = idx & 15;
            float4 v = *(const float4*)(W + (size_t)n * KDIM + kt + q * 4);
            *(float4*)&Ws[n * WS_STRIDE + q * 4] = v;
        }
        __syncthreads();
#pragma unroll
        for (int k8 = 0; k8 < 8; k8++) {
            int kg = kt + k8 * 8;
            unsigned af[2][4];
#pragma unroll
            for (int i = 0; i < 2; i++) {
                const float* Alo = A + (size_t)rlo[i] * KDIM + kg + tig;
                const float* Ahi = A + (size_t)rhi[i] * KDIM + kg + tig;
                float a0 = vlo[i] ? Alo[0] : 0.f;
                float a1 = vhi[i] ? Ahi[0] : 0.f;
                float a2 = vlo[i] ? Alo[4] : 0.f;
                float a3 = vhi[i] ? Ahi[4] : 0.f;
                af[i][0] = f2tf32(a0); af[i][1] = f2tf32(a1);
                af[i][2] = f2tf32(a2); af[i][3] = f2tf32(a3);
            }
#pragma unroll
            for (int j = 0; j < 4; j++) {
                int n = nbase + j * 8 + gid;
                unsigned b0 = f2tf32(Ws[n * WS_STRIDE + k8 * 8 + tig]);
                unsigned b1 = f2tf32(Ws[n * WS_STRIDE + k8 * 8 + tig + 4]);
#pragma unroll
                for (int i = 0; i < 2; i++)
                    mma_tf32(acc[i][j], af[i][0], af[i][1], af[i][2], af[i][3], b0, b1);
            }
        }
    }

    if (bias) {
#pragma unroll
        for (int j = 0; j < 4; j++) {
            int col = nbase + j * 8 + 2 * tig;
            float bv0 = bias[col], bv1 = bias[col + 1];
#pragma unroll
            for (int i = 0; i < 2; i++) {
                acc[i][j][0] += bv0; acc[i][j][1] += bv1;
                acc[i][j][2] += bv0; acc[i][j][3] += bv1;
            }
        }
    }

    float mul_lo[2], mul_hi[2];
#pragma unroll
    for (int i = 0; i < 2; i++) { mul_lo[i] = 1.f; mul_hi[i] = 1.f; }

    if (NORM) {
        __syncthreads();
        if (tid < 64) ssq[tid] = 0.f;
        __syncthreads();
#pragma unroll
        for (int i = 0; i < 2; i++) {
            float plo = 0.f, phi = 0.f;
#pragma unroll
            for (int j = 0; j < 4; j++) {
                plo += acc[i][j][0] * acc[i][j][0] + acc[i][j][1] * acc[i][j][1];
                phi += acc[i][j][2] * acc[i][j][2] + acc[i][j][3] * acc[i][j][3];
            }
            plo += __shfl_xor_sync(0xffffffffu, plo, 1);
            plo += __shfl_xor_sync(0xffffffffu, plo, 2);
            phi += __shfl_xor_sync(0xffffffffu, phi, 1);
            phi += __shfl_xor_sync(0xffffffffu, phi, 2);
            if (tig == 0) {
                atomicAdd(&ssq[wm * 32 + i * 16 + gid], plo);
                atomicAdd(&ssq[wm * 32 + i * 16 + gid + 8], phi);
            }
        }
        __syncthreads();
#pragma unroll
        for (int i = 0; i < 2; i++) {
            mul_lo[i] = scale / fmaxf(sqrtf(ssq[wm * 32 + i * 16 + gid]), 1e-12f);
            mul_hi[i] = scale / fmaxf(sqrtf(ssq[wm * 32 + i * 16 + gid + 8]), 1e-12f);
        }
    }
    if (ROWSCALE) {
#pragma unroll
        for (int i = 0; i < 2; i++) {
            if (vlo[i]) mul_lo[i] *= rs[rlo[i]];
            if (vhi[i]) mul_hi[i] *= rs[rhi[i]];
        }
    }

#pragma unroll
    for (int i = 0; i < 2; i++) {
#pragma unroll
        for (int j = 0; j < 4; j++) {
            int col = nbase + j * 8 + 2 * tig;
            if (vlo[i]) {
                float2 o = make_float2(acc[i][j][0] * mul_lo[i], acc[i][j][1] * mul_lo[i]);
                *(float2*)(out + (size_t)rlo[i] * CH + col) = o;
            }
            if (vhi[i]) {
                float2 o = make_float2(acc[i][j][2] * mul_hi[i], acc[i][j][3] * mul_hi[i]);
                *(float2*)(out + (size_t)rhi[i] * CH + col) = o;
            }
        }
    }
}

// ---------------- z2 body: 4 rows per block, depth-2 register-pipelined DRAM stream ----------------
__device__ __forceinline__ void z2_body4(const float* __restrict__ x2,
                                         const float* __restrict__ W22,
                                         int row0, float* smem) {
    const int tid = threadIdx.x, lane = tid & 31, wid = tid >> 5;
    const int NV = N_NODES / 4;   // 2500 float4 per row; 10 chunks of 256
    const float4* __restrict__ w0 = (const float4*)W22;
    const float4* __restrict__ w1 = (const float4*)(W22 + N_NODES);
    const float4* xr[4];
#pragma unroll
    for (int k = 0; k < 4; k++)
        xr[k] = (const float4*)(x2 + (size_t)(row0 + k) * N_NODES);

    float s0[4] = {0.f, 0.f, 0.f, 0.f}, s1[4] = {0.f, 0.f, 0.f, 0.f};
    float4 a[4], an[4], an2[4];

#pragma unroll
    for (int k = 0; k < 4; k++) a[k]  = xr[k][tid];
#pragma unroll
    for (int k = 0; k < 4; k++) an[k] = xr[k][256 + tid];

    int j = tid;
#pragma unroll
    for (int c = 0; c < 10; c++) {
        bool v = j < NV;
        int js = v ? j : 0;
        float4 b = w0[js], cc = w1[js];
        if (!v) { b = make_float4(0.f,0.f,0.f,0.f); cc = make_float4(0.f,0.f,0.f,0.f); }
        if (c < 8) {
            int jp = j + 512;
            int jps = (jp < NV) ? jp : 0;
#pragma unroll
            for (int k = 0; k < 4; k++) an2[k] = xr[k][jps];
        }
#pragma unroll
        for (int k = 0; k < 4; k++) {
            s0[k] += a[k].x * b.x  + a[k].y * b.y  + a[k].z * b.z  + a[k].w * b.w;
            s1[k] += a[k].x * cc.x + a[k].y * cc.y + a[k].z * cc.z + a[k].w * cc.w;
        }
#pragma unroll
        for (int k = 0; k < 4; k++) { a[k] = an[k]; an[k] = an2[k]; }
        j += 256;
    }

#pragma unroll
    for (int k = 0; k < 4; k++) {
#pragma unroll
        for (int d = 16; d; d >>= 1) {
            s0[k] += __shfl_xor_sync(0xffffffffu, s0[k], d);
            s1[k] += __shfl_xor_sync(0xffffffffu, s1[k], d);
        }
    }
    float* r0 = smem;        // [4][8]
    float* r1 = smem + 32;   // [4][8]
    if (lane == 0) {
#pragma unroll
        for (int k = 0; k < 4; k++) { r0[k * 8 + wid] = s0[k]; r1[k * 8 + wid] = s1[k]; }
    }
    __syncthreads();
    if (tid < 4) {
        float y0 = 0.f, y1 = 0.f;
#pragma unroll
        for (int q = 0; q < 8; q++) { y0 += r0[tid * 8 + q]; y1 += r1[tid * 8 + q]; }
        float n = fmaxf(sqrtf(y0 * y0 + y1 * y1), 1e-12f);
        g_z2c0[row0 + tid] = 0.8f * y0 / n;
    }
}

// ---------------- fatA: gemm1 + cvt_count + z2 rows [0, 3300) ----------------
__global__ __launch_bounds__(256) void fatA_kernel(
    const float* __restrict__ x, const float* __restrict__ W2,
    const float* __restrict__ b2, const int* __restrict__ edge,
    const float* __restrict__ x2, const float* __restrict__ W22) {
    __shared__ float smem[SMEM_FLOATS];
    int b = blockIdx.x;
    if (b < GEMM_BLOCKS) {
        gemm_tf32_body<IN_DIM, true, false>(x, W2, b2, nullptr, g_h,
                                            N_NODES, 1.8f, b * 64, smem);
    } else if (b < GEMM_BLOCKS + AUX_BLOCKS) {
        cvt_count_body(edge, b - GEMM_BLOCKS);
    } else {
        z2_body4(x2, W22, (b - GEMM_BLOCKS - AUX_BLOCKS) * 4, smem);
    }
}

// ---------------- fatB: gemm2 + CSR fill + z2 rows [3300, 6800) ----------------
__global__ __launch_bounds__(256) void fatB_kernel(
    const float* __restrict__ Wg,
    const float* __restrict__ x2, const float* __restrict__ W22) {
    __shared__ float smem[SMEM_FLOATS];
    int b = blockIdx.x;
    if (b < GEMM_BLOCKS) {
        gemm_tf32_body<CH, false, true>(g_h, Wg, nullptr, g_dinv, g_xw,
                                        N_NODES, 1.0f, b * 64, smem);
    } else if (b < GEMM_BLOCKS + AUX_BLOCKS) {
        int bb = b - GEMM_BLOCKS;
        for (int e = threadIdx.x + bb * 256; e < N_EDGES; e += AUX_BLOCKS * 256) {
            int t = g_tgt[e];
            int p = atomicAdd(&g_pos[t], 1);
            int w = g_off[t] + p;
            g_adj[w] = g_src[e];
            g_eid[w] = e;
        }
    } else {
        z2_body4(x2, W22, 3300 + (b - GEMM_BLOCKS - AUX_BLOCKS) * 4, smem);
    }
}

// ---------------- gather: warp per node, float4 per lane (4 channels) ----------------
__device__ __forceinline__ void gather_body_warp(const float* __restrict__ bg,
                                                 int node) {
    int lane = threadIdx.x & 31;
    float4 acc = *(const float4*)(g_xw + (size_t)node * CH + lane * 4);
    int s0 = g_off[node], s1 = g_off[node + 1];
    int j = s0;
    for (; j + 4 <= s1; j += 4) {
        int a0 = g_adj[j], a1 = g_adj[j + 1], a2 = g_adj[j + 2], a3 = g_adj[j + 3];
        float4 v0 = *(const float4*)(g_xw + (size_t)a0 * CH + lane * 4);
        float4 v1 = *(const float4*)(g_xw + (size_t)a1 * CH + lane * 4);
        float4 v2 = *(const float4*)(g_xw + (size_t)a2 * CH + lane * 4);
        float4 v3 = *(const float4*)(g_xw + (size_t)a3 * CH + lane * 4);
        acc.x += (v0.x + v1.x) + (v2.x + v3.x);
        acc.y += (v0.y + v1.y) + (v2.y + v3.y);
        acc.z += (v0.z + v1.z) + (v2.z + v3.z);
        acc.w += (v0.w + v1.w) + (v2.w + v3.w);
    }
    for (; j < s1; j++) {
        float4 v = *(const float4*)(g_xw + (size_t)g_adj[j] * CH + lane * 4);
        acc.x += v.x; acc.y += v.y; acc.z += v.z; acc.w += v.w;
    }
    float di = g_dinv[node];
    float4 bgv = *(const float4*)(bg + lane * 4);
    float4 o;
    o.x = acc.x * di + bgv.x;
    o.y = acc.y * di + bgv.y;
    o.z = acc.z * di + bgv.z;
    o.w = acc.w * di + bgv.w;
    *(float4*)(g_z1 + (size_t)node * CH + lane * 4) = o;
}

// ---------------- fatC: gather (8 nodes/block, first) + z2 rows [6800, 10000) ----------------
#define GATHER_BLOCKS 1250
__global__ __launch_bounds__(256) void fatC_kernel(
    const float* __restrict__ bg,
    const float* __restrict__ x2, const float* __restrict__ W22) {
    __shared__ float smem[SMEM_FLOATS];
    int b = blockIdx.x;
    if (b < GATHER_BLOCKS) {
        int node = b * 8 + (threadIdx.x >> 5);
        if (node < N_NODES) gather_body_warp(bg, node);
    } else {
        z2_body4(x2, W22, 6800 + (b - GATHER_BLOCKS) * 4, smem);
    }
}

// ---------------- decoder: warp per target node, CSR order, 4-edge unroll ----------------
__global__ __launch_bounds__(256) void decoder_kernel(float* __restrict__ out) {
    int gtid = blockIdx.x * blockDim.x + threadIdx.x;
    if (gtid < N_NODES) { g_cnt[gtid] = 0; g_pos[gtid] = 0; }

    int node = gtid >> 5;
    int lane = threadIdx.x & 31;
    if (node >= N_NODES) return;
    float4 zc = *(const float4*)(g_z1 + (size_t)node * CH + lane * 4);
    float zc0 = g_z2c0[node];
    int s0 = g_off[node], s1 = g_off[node + 1];
    int j = s0;
    for (; j + 4 <= s1; j += 4) {
        int sn[4]; float d[4];
#pragma unroll
        for (int k = 0; k < 4; k++) sn[k] = g_adj[j + k];
#pragma unroll
        for (int k = 0; k < 4; k++) {
            const float4 a = *(const float4*)(g_z1 + (size_t)sn[k] * CH + lane * 4);
            d[k] = a.x * zc.x + a.y * zc.y + a.z * zc.z + a.w * zc.w;
        }
#pragma unroll
        for (int o = 16; o; o >>= 1) {
#pragma unroll
            for (int k = 0; k < 4; k++)
                d[k] += __shfl_xor_sync(0xffffffffu, d[k], o);
        }
        if (lane == 0) {
#pragma unroll
            for (int k = 0; k < 4; k++) {
                float vn = g_z2c0[sn[k]] + zc0;
                float sf = 1.f / (1.f + __expf(-d[k]));
                float sg = 1.f / (1.f + __expf(-vn));
                out[g_eid[j + k]] = sf * sf + (1.f - sf) * sg;
            }
        }
    }
    for (; j < s1; j++) {
        int s = g_adj[j];
        const float4 a = *(const float4*)(g_z1 + (size_t)s * CH + lane * 4);
        float d = a.x * zc.x + a.y * zc.y + a.z * zc.z + a.w * zc.w;
#pragma unroll
        for (int o = 16; o; o >>= 1) d += __shfl_xor_sync(0xffffffffu, d, o);
        if (lane == 0) {
            float vn = g_z2c0[s] + zc0;
            float sf = 1.f / (1.f + __expf(-d));
            float sg = 1.f / (1.f + __expf(-vn));
            out[g_eid[j]] = sf * sf + (1.f - sf) * sg;
        }
    }
}

// ---------------- launch ----------------
extern "C" void kernel_launch(void* const* d_in, const int* in_sizes, int n_in,
                              void* d_out, int out_size) {
    const float* x    = (const float*)d_in[0];
    const float* x2   = (const float*)d_in[1];
    const float* W2   = (const float*)d_in[2];
    const float* b2   = (const float*)d_in[3];
    const float* Wg   = (const float*)d_in[4];
    const float* bg   = (const float*)d_in[5];
    const float* W22  = (const float*)d_in[6];
    const int*   edge = (const int*)d_in[7];
    float* out = (float*)d_out;

    fatA_kernel<<<GEMM_BLOCKS + AUX_BLOCKS + Z2A_BLK, 256>>>(x, W2, b2, edge, x2, W22);
    scan_kernel<<<1, 1024>>>();
    fatB_kernel<<<GEMM_BLOCKS + AUX_BLOCKS + Z2B_BLK, 256>>>(Wg, x2, W22);
    fatC_kernel<<<GATHER_BLOCKS + Z2C_BLK, 256>>>(bg, x2, W22);
    decoder_kernel<<<(N_NODES * 32 + 255) / 256, 256>>>(out);
}

// round 13
// speedup vs baseline: 1.4119x; 1.0497x over previous
#include <cuda_runtime.h>
#include <stdint.h>
#include <math.h>

#define N_NODES 10000
#define N_EDGES 320000
#define IN_DIM  512
#define CH      128

// ---------------- scratch (device globals; zero-initialized at load) ----------------
__device__ float g_h  [N_NODES * CH];
__device__ float g_xw [N_NODES * CH];
__device__ float g_z1 [N_NODES * CH];
__device__ float g_dinv[N_NODES];
__device__ int   g_cnt [N_NODES];       // re-zeroed by final kernel each run
__device__ int   g_pos [N_NODES];       // re-zeroed by final kernel each run
__device__ int   g_off [N_NODES + 1];
__device__ int   g_src [N_EDGES];
__device__ int   g_tgt [N_EDGES];
__device__ int   g_adj [N_EDGES];
__device__ int   g_eid [N_EDGES];
__device__ float g_sf  [N_EDGES];       // sigmoid(value_feature), by original edge id
__device__ float g_z2c0[N_NODES];

// z2: 4 rows per block; static slices across four fat kernels
#define Z2A_BLK 725    // rows [0, 2900)
#define Z2B_BLK 775    // rows [2900, 6000)
#define Z2C_BLK 600    // rows [6000, 8400)
#define Z2D_BLK 400    // rows [8400, 10000)

#define GEMM_BLOCKS 157
#define AUX_BLOCKS  64          // cvt_count role (fatA) / fill role (fatB)

// ---------------- edge conversion (role inside fatA) ----------------
__device__ __forceinline__ bool edges_are_i64(const int* p) {
    bool b = true;
#pragma unroll
    for (int i = 0; i < 8; i++) b = b && (p[2 * i + 1] == 0);
    return b;
}

__device__ __forceinline__ void cvt_count_body(const int* __restrict__ ep, int bb) {
    bool i64 = edges_are_i64(ep);
    for (int e = threadIdx.x + bb * 256; e < N_EDGES; e += AUX_BLOCKS * 256) {
        int s, t;
        if (i64) {
            const long long* p = (const long long*)ep;
            s = (int)p[e]; t = (int)p[N_EDGES + e];
        } else {
            s = ep[e]; t = ep[N_EDGES + e];
        }
        g_src[e] = s; g_tgt[e] = t;
        atomicAdd(&g_cnt[t], 1);
    }
}

// ---------------- scan: exclusive prefix of cnt -> off, dinv = rsqrt(cnt+1) ----------------
__global__ void scan_kernel() {
    __shared__ int wsum[32];
    int tid = threadIdx.x, lane = tid & 31, wid = tid >> 5;
    int carry = 0;
    for (int base = 0; base < N_NODES; base += 1024) {
        int idx = base + tid;
        int v = (idx < N_NODES) ? g_cnt[idx] : 0;
        int x = v;
#pragma unroll
        for (int d = 1; d < 32; d <<= 1) {
            int y = __shfl_up_sync(0xffffffffu, x, d);
            if (lane >= d) x += y;
        }
        if (lane == 31) wsum[wid] = x;
        __syncthreads();
        if (wid == 0) {
            int s = wsum[lane];
#pragma unroll
            for (int d = 1; d < 32; d <<= 1) {
                int y = __shfl_up_sync(0xffffffffu, s, d);
                if (lane >= d) s += y;
            }
            wsum[lane] = s;
        }
        __syncthreads();
        int offset = wid ? wsum[wid - 1] : 0;
        if (idx < N_NODES) {
            g_off[idx] = carry + offset + x - v;
            g_dinv[idx] = rsqrtf((float)(v + 1));
        }
        carry += wsum[31];
        __syncthreads();
    }
    if (tid == 0) g_off[N_NODES] = carry;
}

// ---------------- tf32 MMA helpers ----------------
__device__ __forceinline__ unsigned f2tf32(float f) {
    unsigned u;
    asm("cvt.rna.tf32.f32 %0, %1;" : "=r"(u) : "f"(f));
    return u;
}

__device__ __forceinline__ void mma_tf32(float c[4], unsigned a0, unsigned a1,
                                         unsigned a2, unsigned a3,
                                         unsigned b0, unsigned b1) {
    asm volatile(
        "mma.sync.aligned.m16n8k8.row.col.f32.tf32.tf32.f32 "
        "{%0,%1,%2,%3}, {%4,%5,%6,%7}, {%8,%9}, {%0,%1,%2,%3};\n"
        : "+f"(c[0]), "+f"(c[1]), "+f"(c[2]), "+f"(c[3])
        : "r"(a0), "r"(a1), "r"(a2), "r"(a3), "r"(b0), "r"(b1));
}

#define WS_STRIDE 68
#define SMEM_FLOATS (128 * WS_STRIDE + 64)

// ---------------- tf32 GEMM block body: out[M,128] = A[M,K] @ W[128,K]^T ----------------
template <int KDIM, bool NORM, bool ROWSCALE>
__device__ __forceinline__ void gemm_tf32_body(
    const float* __restrict__ A, const float* __restrict__ W,
    const float* __restrict__ bias, const float* __restrict__ rs,
    float* __restrict__ out, int M, float scale, int m0, float* smem) {

    const int tid = threadIdx.x, lane = tid & 31, w = tid >> 5;
    const int gid = lane >> 2, tig = lane & 3;
    const int wm = w & 1, wn = w >> 1;
    const int mbase = m0 + wm * 32;
    const int nbase = wn * 32;
    float* Ws = smem;
    float* ssq = smem + 128 * WS_STRIDE;

    float acc[2][4][4];
#pragma unroll
    for (int i = 0; i < 2; i++)
#pragma unroll
        for (int j = 0; j < 4; j++)
#pragma unroll
            for (int q = 0; q < 4; q++) acc[i][j][q] = 0.f;

    bool vlo[2], vhi[2];
    int rlo[2], rhi[2];
#pragma unroll
    for (int i = 0; i < 2; i++) {
        rlo[i] = mbase + i * 16 + gid;
        rhi[i] = rlo[i] + 8;
        vlo[i] = rlo[i] < M;
        vhi[i] = rhi[i] < M;
    }

    for (int kt = 0; kt < KDIM; kt += 64) {
        __syncthreads();
#pragma unroll
        for (int it = 0; it < 8; it++) {
            int idx = tid + it * 256;
            int n = idx >> 4, q = idx & 15;
            float4 v = *(const float4*)(W + (size_t)n * KDIM + kt + q * 4);
            *(float4*)&Ws[n * WS_STRIDE + q * 4] = v;
        }
        __syncthreads();
#pragma unroll
        for (int k8 = 0; k8 < 8; k8++) {
            int kg = kt + k8 * 8;
            unsigned af[2][4];
#pragma unroll
            for (int i = 0; i < 2; i++) {
                const float* Alo = A + (size_t)rlo[i] * KDIM + kg + tig;
                const float* Ahi = A + (size_t)rhi[i] * KDIM + kg + tig;
                float a0 = vlo[i] ? Alo[0] : 0.f;
                float a1 = vhi[i] ? Ahi[0] : 0.f;
                float a2 = vlo[i] ? Alo[4] : 0.f;
                float a3 = vhi[i] ? Ahi[4] : 0.f;
                af[i][0] = f2tf32(a0); af[i][1] = f2tf32(a1);
                af[i][2] = f2tf32(a2); af[i][3] = f2tf32(a3);
            }
#pragma unroll
            for (int j = 0; j < 4; j++) {
                int n = nbase + j * 8 + gid;
                unsigned b0 = f2tf32(Ws[n * WS_STRIDE + k8 * 8 + tig]);
                unsigned b1 = f2tf32(Ws[n * WS_STRIDE + k8 * 8 + tig + 4]);
#pragma unroll
                for (int i = 0; i < 2; i++)
                    mma_tf32(acc[i][j], af[i][0], af[i][1], af[i][2], af[i][3], b0, b1);
            }
        }
    }

    if (bias) {
#pragma unroll
        for (int j = 0; j < 4; j++) {
            int col = nbase + j * 8 + 2 * tig;
            float bv0 = bias[col], bv1 = bias[col + 1];
#pragma unroll
            for (int i = 0; i < 2; i++) {
                acc[i][j][0] += bv0; acc[i][j][1] += bv1;
                acc[i][j][2] += bv0; acc[i][j][3] += bv1;
            }
        }
    }

    float mul_lo[2], mul_hi[2];
#pragma unroll
    for (int i = 0; i < 2; i++) { mul_lo[i] = 1.f; mul_hi[i] = 1.f; }

    if (NORM) {
        __syncthreads();
        if (tid < 64) ssq[tid] = 0.f;
        __syncthreads();
#pragma unroll
        for (int i = 0; i < 2; i++) {
            float plo = 0.f, phi = 0.f;
#pragma unroll
            for (int j = 0; j < 4; j++) {
                plo += acc[i][j][0] * acc[i][j][0] + acc[i][j][1] * acc[i][j][1];
                phi += acc[i][j][2] * acc[i][j][2] + acc[i][j][3] * acc[i][j][3];
            }
            plo += __shfl_xor_sync(0xffffffffu, plo, 1);
            plo += __shfl_xor_sync(0xffffffffu, plo, 2);
            phi += __shfl_xor_sync(0xffffffffu, phi, 1);
            phi += __shfl_xor_sync(0xffffffffu, phi, 2);
            if (tig == 0) {
                atomicAdd(&ssq[wm * 32 + i * 16 + gid], plo);
                atomicAdd(&ssq[wm * 32 + i * 16 + gid + 8], phi);
            }
        }
        __syncthreads();
#pragma unroll
        for (int i = 0; i < 2; i++) {
            mul_lo[i] = scale / fmaxf(sqrtf(ssq[wm * 32 + i * 16 + gid]), 1e-12f);
            mul_hi[i] = scale / fmaxf(sqrtf(ssq[wm * 32 + i * 16 + gid + 8]), 1e-12f);
        }
    }
    if (ROWSCALE) {
#pragma unroll
        for (int i = 0; i < 2; i++) {
            if (vlo[i]) mul_lo[i] *= rs[rlo[i]];
            if (vhi[i]) mul_hi[i] *= rs[rhi[i]];
        }
    }

#pragma unroll
    for (int i = 0; i < 2; i++) {
#pragma unroll
        for (int j = 0; j < 4; j++) {
            int col = nbase + j * 8 + 2 * tig;
            if (vlo[i]) {
                float2 o = make_float2(acc[i][j][0] * mul_lo[i], acc[i][j][1] * mul_lo[i]);
                *(float2*)(out + (size_t)rlo[i] * CH + col) = o;
            }
            if (vhi[i]) {
                float2 o = make_float2(acc[i][j][2] * mul_hi[i], acc[i][j][3] * mul_hi[i]);
                *(float2*)(out + (size_t)rhi[i] * CH + col) = o;
            }
        }
    }
}

// ---------------- z2 body: 4 rows per block, depth-2 register-pipelined DRAM stream ----------------
__device__ __forceinline__ void z2_body4(const float* __restrict__ x2,
                                         const float* __restrict__ W22,
                                         int row0, float* smem) {
    const int tid = threadIdx.x, lane = tid & 31, wid = tid >> 5;
    const int NV = N_NODES / 4;   // 2500 float4 per row; 10 chunks of 256
    const float4* __restrict__ w0 = (const float4*)W22;
    const float4* __restrict__ w1 = (const float4*)(W22 + N_NODES);
    const float4* xr[4];
#pragma unroll
    for (int k = 0; k < 4; k++)
        xr[k] = (const float4*)(x2 + (size_t)(row0 + k) * N_NODES);

    float s0[4] = {0.f, 0.f, 0.f, 0.f}, s1[4] = {0.f, 0.f, 0.f, 0.f};
    float4 a[4], an[4], an2[4];

#pragma unroll
    for (int k = 0; k < 4; k++) a[k]  = xr[k][tid];
#pragma unroll
    for (int k = 0; k < 4; k++) an[k] = xr[k][256 + tid];

    int j = tid;
#pragma unroll
    for (int c = 0; c < 10; c++) {
        bool v = j < NV;
        int js = v ? j : 0;
        float4 b = w0[js], cc = w1[js];
        if (!v) { b = make_float4(0.f,0.f,0.f,0.f); cc = make_float4(0.f,0.f,0.f,0.f); }
        if (c < 8) {
            int jp = j + 512;
            int jps = (jp < NV) ? jp : 0;
#pragma unroll
            for (int k = 0; k < 4; k++) an2[k] = xr[k][jps];
        }
#pragma unroll
        for (int k = 0; k < 4; k++) {
            s0[k] += a[k].x * b.x  + a[k].y * b.y  + a[k].z * b.z  + a[k].w * b.w;
            s1[k] += a[k].x * cc.x + a[k].y * cc.y + a[k].z * cc.z + a[k].w * cc.w;
        }
#pragma unroll
        for (int k = 0; k < 4; k++) { a[k] = an[k]; an[k] = an2[k]; }
        j += 256;
    }

#pragma unroll
    for (int k = 0; k < 4; k++) {
#pragma unroll
        for (int d = 16; d; d >>= 1) {
            s0[k] += __shfl_xor_sync(0xffffffffu, s0[k], d);
            s1[k] += __shfl_xor_sync(0xffffffffu, s1[k], d);
        }
    }
    float* r0 = smem;        // [4][8]
    float* r1 = smem + 32;   // [4][8]
    if (lane == 0) {
#pragma unroll
        for (int k = 0; k < 4; k++) { r0[k * 8 + wid] = s0[k]; r1[k * 8 + wid] = s1[k]; }
    }
    __syncthreads();
    if (tid < 4) {
        float y0 = 0.f, y1 = 0.f;
#pragma unroll
        for (int q = 0; q < 8; q++) { y0 += r0[tid * 8 + q]; y1 += r1[tid * 8 + q]; }
        float n = fmaxf(sqrtf(y0 * y0 + y1 * y1), 1e-12f);
        g_z2c0[row0 + tid] = 0.8f * y0 / n;
    }
}

// ---------------- fatA: gemm1 + cvt_count + z2 rows [0, 2900) ----------------
__global__ __launch_bounds__(256) void fatA_kernel(
    const float* __restrict__ x, const float* __restrict__ W2,
    const float* __restrict__ b2, const int* __restrict__ edge,
    const float* __restrict__ x2, const float* __restrict__ W22) {
    __shared__ float smem[SMEM_FLOATS];
    int b = blockIdx.x;
    if (b < GEMM_BLOCKS) {
        gemm_tf32_body<IN_DIM, true, false>(x, W2, b2, nullptr, g_h,
                                            N_NODES, 1.8f, b * 64, smem);
    } else if (b < GEMM_BLOCKS + AUX_BLOCKS) {
        cvt_count_body(edge, b - GEMM_BLOCKS);
    } else {
        z2_body4(x2, W22, (b - GEMM_BLOCKS - AUX_BLOCKS) * 4, smem);
    }
}

// ---------------- fatB: gemm2 + CSR fill + z2 rows [2900, 6000) ----------------
__global__ __launch_bounds__(256) void fatB_kernel(
    const float* __restrict__ Wg,
    const float* __restrict__ x2, const float* __restrict__ W22) {
    __shared__ float smem[SMEM_FLOATS];
    int b = blockIdx.x;
    if (b < GEMM_BLOCKS) {
        gemm_tf32_body<CH, false, true>(g_h, Wg, nullptr, g_dinv, g_xw,
                                        N_NODES, 1.0f, b * 64, smem);
    } else if (b < GEMM_BLOCKS + AUX_BLOCKS) {
        int bb = b - GEMM_BLOCKS;
        for (int e = threadIdx.x + bb * 256; e < N_EDGES; e += AUX_BLOCKS * 256) {
            int t = g_tgt[e];
            int p = atomicAdd(&g_pos[t], 1);
            int w = g_off[t] + p;
            g_adj[w] = g_src[e];
            g_eid[w] = e;
        }
    } else {
        z2_body4(x2, W22, 2900 + (b - GEMM_BLOCKS - AUX_BLOCKS) * 4, smem);
    }
}

// ---------------- gather: warp per node, float4 per lane (4 channels) ----------------
__device__ __forceinline__ void gather_body_warp(const float* __restrict__ bg,
                                                 int node) {
    int lane = threadIdx.x & 31;
    float4 acc = *(const float4*)(g_xw + (size_t)node * CH + lane * 4);
    int s0 = g_off[node], s1 = g_off[node + 1];
    int j = s0;
    for (; j + 4 <= s1; j += 4) {
        int a0 = g_adj[j], a1 = g_adj[j + 1], a2 = g_adj[j + 2], a3 = g_adj[j + 3];
        float4 v0 = *(const float4*)(g_xw + (size_t)a0 * CH + lane * 4);
        float4 v1 = *(const float4*)(g_xw + (size_t)a1 * CH + lane * 4);
        float4 v2 = *(const float4*)(g_xw + (size_t)a2 * CH + lane * 4);
        float4 v3 = *(const float4*)(g_xw + (size_t)a3 * CH + lane * 4);
        acc.x += (v0.x + v1.x) + (v2.x + v3.x);
        acc.y += (v0.y + v1.y) + (v2.y + v3.y);
        acc.z += (v0.z + v1.z) + (v2.z + v3.z);
        acc.w += (v0.w + v1.w) + (v2.w + v3.w);
    }
    for (; j < s1; j++) {
        float4 v = *(const float4*)(g_xw + (size_t)g_adj[j] * CH + lane * 4);
        acc.x += v.x; acc.y += v.y; acc.z += v.z; acc.w += v.w;
    }
    float di = g_dinv[node];
    float4 bgv = *(const float4*)(bg + lane * 4);
    float4 o;
    o.x = acc.x * di + bgv.x;
    o.y = acc.y * di + bgv.y;
    o.z = acc.z * di + bgv.z;
    o.w = acc.w * di + bgv.w;
    *(float4*)(g_z1 + (size_t)node * CH + lane * 4) = o;
}

// ---------------- fatC: gather (8 nodes/block, first) + z2 rows [6000, 8400) ----------------
#define GATHER_BLOCKS 1250
__global__ __launch_bounds__(256) void fatC_kernel(
    const float* __restrict__ bg,
    const float* __restrict__ x2, const float* __restrict__ W22) {
    __shared__ float smem[SMEM_FLOATS];
    int b = blockIdx.x;
    if (b < GATHER_BLOCKS) {
        int node = b * 8 + (threadIdx.x >> 5);
        if (node < N_NODES) gather_body_warp(bg, node);
    } else {
        z2_body4(x2, W22, 6000 + (b - GATHER_BLOCKS) * 4, smem);
    }
}

// ---------------- fatD: decoder-feature (first) + z2 rows [8400, 10000) ----------------
// decf: warp per target node, sf = sigmoid(z1[s].z1[t]) scattered to g_sf[eid], 4-edge unroll
#define DECF_BLOCKS 1250
__global__ __launch_bounds__(256) void fatD_kernel(
    const float* __restrict__ x2, const float* __restrict__ W22) {
    __shared__ float smem[SMEM_FLOATS];
    int b = blockIdx.x;
    if (b < DECF_BLOCKS) {
        int lane = threadIdx.x & 31;
        int node = b * 8 + (threadIdx.x >> 5);
        if (node >= N_NODES) return;
        float4 zc = *(const float4*)(g_z1 + (size_t)node * CH + lane * 4);
        int s0 = g_off[node], s1 = g_off[node + 1];
        int j = s0;
        for (; j + 4 <= s1; j += 4) {
            int sn[4]; float d[4];
#pragma unroll
            for (int k = 0; k < 4; k++) sn[k] = g_adj[j + k];
#pragma unroll
            for (int k = 0; k < 4; k++) {
                const float4 a = *(const float4*)(g_z1 + (size_t)sn[k] * CH + lane * 4);
                d[k] = a.x * zc.x + a.y * zc.y + a.z * zc.z + a.w * zc.w;
            }
#pragma unroll
            for (int o = 16; o; o >>= 1) {
#pragma unroll
                for (int k = 0; k < 4; k++)
                    d[k] += __shfl_xor_sync(0xffffffffu, d[k], o);
            }
            if (lane == 0) {
#pragma unroll
                for (int k = 0; k < 4; k++)
                    g_sf[g_eid[j + k]] = 1.f / (1.f + __expf(-d[k]));
            }
        }
        for (; j < s1; j++) {
            int s = g_adj[j];
            const float4 a = *(const float4*)(g_z1 + (size_t)s * CH + lane * 4);
            float d = a.x * zc.x + a.y * zc.y + a.z * zc.z + a.w * zc.w;
#pragma unroll
            for (int o = 16; o; o >>= 1) d += __shfl_xor_sync(0xffffffffu, d, o);
            if (lane == 0) g_sf[g_eid[j]] = 1.f / (1.f + __expf(-d));
        }
    } else {
        z2_body4(x2, W22, 8400 + (b - DECF_BLOCKS) * 4, smem);
    }
}

// ---------------- final: out = sf^2 + (1-sf)*sigmoid(z2c0[r]+z2c0[c]); reset cnt/pos ----------------
__global__ __launch_bounds__(256) void final_kernel(float* __restrict__ out) {
    int e = blockIdx.x * blockDim.x + threadIdx.x;
    if (e < N_NODES) { g_cnt[e] = 0; g_pos[e] = 0; }
    if (e >= N_EDGES) return;
    float sf = g_sf[e];
    float vn = g_z2c0[g_src[e]] + g_z2c0[g_tgt[e]];
    float sn = 1.f / (1.f + __expf(-vn));
    out[e] = sf * sf + (1.f - sf) * sn;
}

// ---------------- launch ----------------
extern "C" void kernel_launch(void* const* d_in, const int* in_sizes, int n_in,
                              void* d_out, int out_size) {
    const float* x    = (const float*)d_in[0];
    const float* x2   = (const float*)d_in[1];
    const float* W2   = (const float*)d_in[2];
    const float* b2   = (const float*)d_in[3];
    const float* Wg   = (const float*)d_in[4];
    const float* bg   = (const float*)d_in[5];
    const float* W22  = (const float*)d_in[6];
    const int*   edge = (const int*)d_in[7];
    float* out = (float*)d_out;

    fatA_kernel<<<GEMM_BLOCKS + AUX_BLOCKS + Z2A_BLK, 256>>>(x, W2, b2, edge, x2, W22);
    scan_kernel<<<1, 1024>>>();
    fatB_kernel<<<GEMM_BLOCKS + AUX_BLOCKS + Z2B_BLK, 256>>>(Wg, x2, W22);
    fatC_kernel<<<GATHER_BLOCKS + Z2C_BLK, 256>>>(bg, x2, W22);
    fatD_kernel<<<DECF_BLOCKS + Z2D_BLK, 256>>>(x2, W22);
    final_kernel<<<(N_EDGES + 255) / 256, 256>>>(out);
}

// round 14
// speedup vs baseline: 1.5296x; 1.0834x over previous
#include <cuda_runtime.h>
#include <stdint.h>
#include <math.h>

#define N_NODES 10000
#define N_EDGES 320000
#define IN_DIM  512
#define CH      128

// ---------------- scratch (device globals; zero-initialized at load) ----------------
__device__ float g_h  [N_NODES * CH];
__device__ float g_xw [N_NODES * CH];
__device__ float g_z1 [N_NODES * CH];
__device__ float g_dinv[N_NODES];
__device__ int   g_cnt [N_NODES];       // re-zeroed by final kernel each run
__device__ int   g_pos [N_NODES];       // re-zeroed by final kernel each run
__device__ int   g_off [N_NODES + 1];
__device__ int   g_src [N_EDGES];
__device__ int   g_tgt [N_EDGES];
__device__ int   g_adj [N_EDGES];
__device__ int   g_eid [N_EDGES];
__device__ float g_sf  [N_EDGES];       // sigmoid(value_feature), by original edge id
__device__ float g_z2c0[N_NODES];
__device__ int   ct_cvt;                // cvt completion counter (reset in final)

// z2: 4 rows per block; static slices across four fat kernels
#define Z2A_BLK 700    // rows [0, 2800)
#define Z2B_BLK 800    // rows [2800, 6000)
#define Z2C_BLK 600    // rows [6000, 8400)
#define Z2D_BLK 400    // rows [8400, 10000)

#define GEMM_BLOCKS 157
#define AUX_BLOCKS  64          // cvt_count role (fatA) / fill role (fatB)

// ---------------- edge conversion (role inside fatA) ----------------
__device__ __forceinline__ bool edges_are_i64(const int* p) {
    bool b = true;
#pragma unroll
    for (int i = 0; i < 8; i++) b = b && (p[2 * i + 1] == 0);
    return b;
}

__device__ __forceinline__ void cvt_count_body(const int* __restrict__ ep, int bb) {
    bool i64 = edges_are_i64(ep);
    for (int e = threadIdx.x + bb * 256; e < N_EDGES; e += AUX_BLOCKS * 256) {
        int s, t;
        if (i64) {
            const long long* p = (const long long*)ep;
            s = (int)p[e]; t = (int)p[N_EDGES + e];
        } else {
            s = ep[e]; t = ep[N_EDGES + e];
        }
        g_src[e] = s; g_tgt[e] = t;
        atomicAdd(&g_cnt[t], 1);
    }
}

// ---------------- scan body (256 threads): cnt -> off (exclusive), dinv ----------------
__device__ __forceinline__ void scan_body256(int* wsum) {
    int tid = threadIdx.x, lane = tid & 31, wid = tid >> 5;
    int carry = 0;
    for (int base = 0; base < N_NODES; base += 256) {
        int idx = base + tid;
        int v = (idx < N_NODES) ? g_cnt[idx] : 0;
        int x = v;
#pragma unroll
        for (int d = 1; d < 32; d <<= 1) {
            int y = __shfl_up_sync(0xffffffffu, x, d);
            if (lane >= d) x += y;
        }
        if (lane == 31) wsum[wid] = x;
        __syncthreads();
        if (wid == 0 && lane < 8) {
            int s = wsum[lane];
#pragma unroll
            for (int d = 1; d < 8; d <<= 1) {
                int y = __shfl_up_sync(0xffu, s, d);
                if (lane >= d) s += y;
            }
            wsum[lane] = s;
        }
        __syncthreads();
        int offset = wid ? wsum[wid - 1] : 0;
        if (idx < N_NODES) {
            g_off[idx] = carry + offset + x - v;
            g_dinv[idx] = rsqrtf((float)(v + 1));
        }
        carry += wsum[7];
        __syncthreads();
    }
    if (tid == 0) g_off[N_NODES] = carry;
}

// ---------------- tf32 MMA helpers ----------------
__device__ __forceinline__ unsigned f2tf32(float f) {
    unsigned u;
    asm("cvt.rna.tf32.f32 %0, %1;" : "=r"(u) : "f"(f));
    return u;
}

__device__ __forceinline__ void mma_tf32(float c[4], unsigned a0, unsigned a1,
                                         unsigned a2, unsigned a3,
                                         unsigned b0, unsigned b1) {
    asm volatile(
        "mma.sync.aligned.m16n8k8.row.col.f32.tf32.tf32.f32 "
        "{%0,%1,%2,%3}, {%4,%5,%6,%7}, {%8,%9}, {%0,%1,%2,%3};\n"
        : "+f"(c[0]), "+f"(c[1]), "+f"(c[2]), "+f"(c[3])
        : "r"(a0), "r"(a1), "r"(a2), "r"(a3), "r"(b0), "r"(b1));
}

#define WS_STRIDE 68
#define SMEM_FLOATS (128 * WS_STRIDE + 64)

// ---------------- tf32 GEMM block body: out[M,128] = A[M,K] @ W[128,K]^T ----------------
template <int KDIM, bool NORM, bool ROWSCALE>
__device__ __forceinline__ void gemm_tf32_body(
    const float* __restrict__ A, const float* __restrict__ W,
    const float* __restrict__ bias, const float* __restrict__ rs,
    float* __restrict__ out, int M, float scale, int m0, float* smem) {

    const int tid = threadIdx.x, lane = tid & 31, w = tid >> 5;
    const int gid = lane >> 2, tig = lane & 3;
    const int wm = w & 1, wn = w >> 1;
    const int mbase = m0 + wm * 32;
    const int nbase = wn * 32;
    float* Ws = smem;
    float* ssq = smem + 128 * WS_STRIDE;

    float acc[2][4][4];
#pragma unroll
    for (int i = 0; i < 2; i++)
#pragma unroll
        for (int j = 0; j < 4; j++)
#pragma unroll
            for (int q = 0; q < 4; q++) acc[i][j][q] = 0.f;

    bool vlo[2], vhi[2];
    int rlo[2], rhi[2];
#pragma unroll
    for (int i = 0; i < 2; i++) {
        rlo[i] = mbase + i * 16 + gid;
        rhi[i] = rlo[i] + 8;
        vlo[i] = rlo[i] < M;
        vhi[i] = rhi[i] < M;
    }

    for (int kt = 0; kt < KDIM; kt += 64) {
        __syncthreads();
#pragma unroll
        for (int it = 0; it < 8; it++) {
            int idx = tid + it * 256;
            int n = idx >> 4, q = idx & 15;
            float4 v = *(const float4*)(W + (size_t)n * KDIM + kt + q * 4);
            *(float4*)&Ws[n * WS_STRIDE + q * 4] = v;
        }
        __syncthreads();
#pragma unroll
        for (int k8 = 0; k8 < 8; k8++) {
            int kg = kt + k8 * 8;
            unsigned af[2][4];
#pragma unroll
            for (int i = 0; i < 2; i++) {
                const float* Alo = A + (size_t)rlo[i] * KDIM + kg + tig;
                const float* Ahi = A + (size_t)rhi[i] * KDIM + kg + tig;
                float a0 = vlo[i] ? Alo[0] : 0.f;
                float a1 = vhi[i] ? Ahi[0] : 0.f;
                float a2 = vlo[i] ? Alo[4] : 0.f;
                float a3 = vhi[i] ? Ahi[4] : 0.f;
                af[i][0] = f2tf32(a0); af[i][1] = f2tf32(a1);
                af[i][2] = f2tf32(a2); af[i][3] = f2tf32(a3);
            }
#pragma unroll
            for (int j = 0; j < 4; j++) {
                int n = nbase + j * 8 + gid;
                unsigned b0 = f2tf32(Ws[n * WS_STRIDE + k8 * 8 + tig]);
                unsigned b1 = f2tf32(Ws[n * WS_STRIDE + k8 * 8 + tig + 4]);
#pragma unroll
                for (int i = 0; i < 2; i++)
                    mma_tf32(acc[i][j], af[i][0], af[i][1], af[i][2], af[i][3], b0, b1);
            }
        }
    }

    if (bias) {
#pragma unroll
        for (int j = 0; j < 4; j++) {
            int col = nbase + j * 8 + 2 * tig;
            float bv0 = bias[col], bv1 = bias[col + 1];
#pragma unroll
            for (int i = 0; i < 2; i++) {
                acc[i][j][0] += bv0; acc[i][j][1] += bv1;
                acc[i][j][2] += bv0; acc[i][j][3] += bv1;
            }
        }
    }

    float mul_lo[2], mul_hi[2];
#pragma unroll
    for (int i = 0; i < 2; i++) { mul_lo[i] = 1.f; mul_hi[i] = 1.f; }

    if (NORM) {
        __syncthreads();
        if (tid < 64) ssq[tid] = 0.f;
        __syncthreads();
#pragma unroll
        for (int i = 0; i < 2; i++) {
            float plo = 0.f, phi = 0.f;
#pragma unroll
            for (int j = 0; j < 4; j++) {
                plo += acc[i][j][0] * acc[i][j][0] + acc[i][j][1] * acc[i][j][1];
                phi += acc[i][j][2] * acc[i][j][2] + acc[i][j][3] * acc[i][j][3];
            }
            plo += __shfl_xor_sync(0xffffffffu, plo, 1);
            plo += __shfl_xor_sync(0xffffffffu, plo, 2);
            phi += __shfl_xor_sync(0xffffffffu, phi, 1);
            phi += __shfl_xor_sync(0xffffffffu, phi, 2);
            if (tig == 0) {
                atomicAdd(&ssq[wm * 32 + i * 16 + gid], plo);
                atomicAdd(&ssq[wm * 32 + i * 16 + gid + 8], phi);
            }
        }
        __syncthreads();
#pragma unroll
        for (int i = 0; i < 2; i++) {
            mul_lo[i] = scale / fmaxf(sqrtf(ssq[wm * 32 + i * 16 + gid]), 1e-12f);
            mul_hi[i] = scale / fmaxf(sqrtf(ssq[wm * 32 + i * 16 + gid + 8]), 1e-12f);
        }
    }
    if (ROWSCALE) {
#pragma unroll
        for (int i = 0; i < 2; i++) {
            if (vlo[i]) mul_lo[i] *= rs[rlo[i]];
            if (vhi[i]) mul_hi[i] *= rs[rhi[i]];
        }
    }

#pragma unroll
    for (int i = 0; i < 2; i++) {
#pragma unroll
        for (int j = 0; j < 4; j++) {
            int col = nbase + j * 8 + 2 * tig;
            if (vlo[i]) {
                float2 o = make_float2(acc[i][j][0] * mul_lo[i], acc[i][j][1] * mul_lo[i]);
                *(float2*)(out + (size_t)rlo[i] * CH + col) = o;
            }
            if (vhi[i]) {
                float2 o = make_float2(acc[i][j][2] * mul_hi[i], acc[i][j][3] * mul_hi[i]);
                *(float2*)(out + (size_t)rhi[i] * CH + col) = o;
            }
        }
    }
}

// ---------------- z2 body: 4 rows per block, depth-2 register-pipelined DRAM stream ----------------
__device__ __forceinline__ void z2_body4(const float* __restrict__ x2,
                                         const float* __restrict__ W22,
                                         int row0, float* smem) {
    const int tid = threadIdx.x, lane = tid & 31, wid = tid >> 5;
    const int NV = N_NODES / 4;   // 2500 float4 per row; 10 chunks of 256
    const float4* __restrict__ w0 = (const float4*)W22;
    const float4* __restrict__ w1 = (const float4*)(W22 + N_NODES);
    const float4* xr[4];
#pragma unroll
    for (int k = 0; k < 4; k++)
        xr[k] = (const float4*)(x2 + (size_t)(row0 + k) * N_NODES);

    float s0[4] = {0.f, 0.f, 0.f, 0.f}, s1[4] = {0.f, 0.f, 0.f, 0.f};
    float4 a[4], an[4], an2[4];

#pragma unroll
    for (int k = 0; k < 4; k++) a[k]  = xr[k][tid];
#pragma unroll
    for (int k = 0; k < 4; k++) an[k] = xr[k][256 + tid];

    int j = tid;
#pragma unroll
    for (int c = 0; c < 10; c++) {
        bool v = j < NV;
        int js = v ? j : 0;
        float4 b = w0[js], cc = w1[js];
        if (!v) { b = make_float4(0.f,0.f,0.f,0.f); cc = make_float4(0.f,0.f,0.f,0.f); }
        if (c < 8) {
            int jp = j + 512;
            int jps = (jp < NV) ? jp : 0;
#pragma unroll
            for (int k = 0; k < 4; k++) an2[k] = xr[k][jps];
        }
#pragma unroll
        for (int k = 0; k < 4; k++) {
            s0[k] += a[k].x * b.x  + a[k].y * b.y  + a[k].z * b.z  + a[k].w * b.w;
            s1[k] += a[k].x * cc.x + a[k].y * cc.y + a[k].z * cc.z + a[k].w * cc.w;
        }
#pragma unroll
        for (int k = 0; k < 4; k++) { a[k] = an[k]; an[k] = an2[k]; }
        j += 256;
    }

#pragma unroll
    for (int k = 0; k < 4; k++) {
#pragma unroll
        for (int d = 16; d; d >>= 1) {
            s0[k] += __shfl_xor_sync(0xffffffffu, s0[k], d);
            s1[k] += __shfl_xor_sync(0xffffffffu, s1[k], d);
        }
    }
    float* r0 = smem;        // [4][8]
    float* r1 = smem + 32;   // [4][8]
    if (lane == 0) {
#pragma unroll
        for (int k = 0; k < 4; k++) { r0[k * 8 + wid] = s0[k]; r1[k * 8 + wid] = s1[k]; }
    }
    __syncthreads();
    if (tid < 4) {
        float y0 = 0.f, y1 = 0.f;
#pragma unroll
        for (int q = 0; q < 8; q++) { y0 += r0[tid * 8 + q]; y1 += r1[tid * 8 + q]; }
        float n = fmaxf(sqrtf(y0 * y0 + y1 * y1), 1e-12f);
        g_z2c0[row0 + tid] = 0.8f * y0 / n;
    }
}

// ---------------- fatA: gemm1 + cvt_count(+scan by last finisher) + z2 rows [0, 2800) ----------------
__global__ __launch_bounds__(256) void fatA_kernel(
    const float* __restrict__ x, const float* __restrict__ W2,
    const float* __restrict__ b2, const int* __restrict__ edge,
    const float* __restrict__ x2, const float* __restrict__ W22) {
    __shared__ float smem[SMEM_FLOATS];
    __shared__ int s_last;
    int b = blockIdx.x;
    if (b < GEMM_BLOCKS) {
        gemm_tf32_body<IN_DIM, true, false>(x, W2, b2, nullptr, g_h,
                                            N_NODES, 1.8f, b * 64, smem);
    } else if (b < GEMM_BLOCKS + AUX_BLOCKS) {
        cvt_count_body(edge, b - GEMM_BLOCKS);
        __threadfence();
        __syncthreads();
        if (threadIdx.x == 0)
            s_last = (atomicAdd(&ct_cvt, 1) == AUX_BLOCKS - 1);
        __syncthreads();
        if (s_last) {
            __threadfence();                 // ensure we see all g_cnt updates
            scan_body256((int*)smem);        // hidden under concurrent z2 stream
        }
    } else {
        z2_body4(x2, W22, (b - GEMM_BLOCKS - AUX_BLOCKS) * 4, smem);
    }
}

// ---------------- fatB: gemm2 + CSR fill + z2 rows [2800, 6000) ----------------
__global__ __launch_bounds__(256) void fatB_kernel(
    const float* __restrict__ Wg,
    const float* __restrict__ x2, const float* __restrict__ W22) {
    __shared__ float smem[SMEM_FLOATS];
    int b = blockIdx.x;
    if (b < GEMM_BLOCKS) {
        gemm_tf32_body<CH, false, true>(g_h, Wg, nullptr, g_dinv, g_xw,
                                        N_NODES, 1.0f, b * 64, smem);
    } else if (b < GEMM_BLOCKS + AUX_BLOCKS) {
        int bb = b - GEMM_BLOCKS;
        for (int e = threadIdx.x + bb * 256; e < N_EDGES; e += AUX_BLOCKS * 256) {
            int t = g_tgt[e];
            int p = atomicAdd(&g_pos[t], 1);
            int w = g_off[t] + p;
            g_adj[w] = g_src[e];
            g_eid[w] = e;
        }
    } else {
        z2_body4(x2, W22, 2800 + (b - GEMM_BLOCKS - AUX_BLOCKS) * 4, smem);
    }
}

// ---------------- gather: warp per node, float4 per lane (4 channels) ----------------
__device__ __forceinline__ void gather_body_warp(const float* __restrict__ bg,
                                                 int node) {
    int lane = threadIdx.x & 31;
    float4 acc = *(const float4*)(g_xw + (size_t)node * CH + lane * 4);
    int s0 = g_off[node], s1 = g_off[node + 1];
    int j = s0;
    for (; j + 4 <= s1; j += 4) {
        int a0 = g_adj[j], a1 = g_adj[j + 1], a2 = g_adj[j + 2], a3 = g_adj[j + 3];
        float4 v0 = *(const float4*)(g_xw + (size_t)a0 * CH + lane * 4);
        float4 v1 = *(const float4*)(g_xw + (size_t)a1 * CH + lane * 4);
        float4 v2 = *(const float4*)(g_xw + (size_t)a2 * CH + lane * 4);
        float4 v3 = *(const float4*)(g_xw + (size_t)a3 * CH + lane * 4);
        acc.x += (v0.x + v1.x) + (v2.x + v3.x);
        acc.y += (v0.y + v1.y) + (v2.y + v3.y);
        acc.z += (v0.z + v1.z) + (v2.z + v3.z);
        acc.w += (v0.w + v1.w) + (v2.w + v3.w);
    }
    for (; j < s1; j++) {
        float4 v = *(const float4*)(g_xw + (size_t)g_adj[j] * CH + lane * 4);
        acc.x += v.x; acc.y += v.y; acc.z += v.z; acc.w += v.w;
    }
    float di = g_dinv[node];
    float4 bgv = *(const float4*)(bg + lane * 4);
    float4 o;
    o.x = acc.x * di + bgv.x;
    o.y = acc.y * di + bgv.y;
    o.z = acc.z * di + bgv.z;
    o.w = acc.w * di + bgv.w;
    *(float4*)(g_z1 + (size_t)node * CH + lane * 4) = o;
}

// ---------------- fatC: interleaved gather (1250) + z2 rows [6000, 8400) (600) ----------------
// every 3rd block (while z2 remains) is a z2 block -> mixed waves keep DRAM busy
#define GATHER_BLOCKS 1250
__global__ __launch_bounds__(256) void fatC_kernel(
    const float* __restrict__ bg,
    const float* __restrict__ x2, const float* __restrict__ W22) {
    __shared__ float smem[SMEM_FLOATS];
    int b = blockIdx.x;
    bool isZ2 = (b < 1800) && (b % 3 == 0);
    if (isZ2) {
        z2_body4(x2, W22, 6000 + (b / 3) * 4, smem);
    } else {
        int zBefore = (b < 1800) ? ((b + 2) / 3) : 600;
        int g = b - zBefore;
        int node = g * 8 + (threadIdx.x >> 5);
        if (node < N_NODES) gather_body_warp(bg, node);
    }
}

// ---------------- fatD: interleaved decf (1250) + z2 rows [8400, 10000) (400) ----------------
// every 4th block (while z2 remains) is a z2 block
#define DECF_BLOCKS 1250
__device__ __forceinline__ void decf_body_warp(int node) {
    int lane = threadIdx.x & 31;
    float4 zc = *(const float4*)(g_z1 + (size_t)node * CH + lane * 4);
    int s0 = g_off[node], s1 = g_off[node + 1];
    int j = s0;
    for (; j + 4 <= s1; j += 4) {
        int sn[4]; float d[4];
#pragma unroll
        for (int k = 0; k < 4; k++) sn[k] = g_adj[j + k];
#pragma unroll
        for (int k = 0; k < 4; k++) {
            const float4 a = *(const float4*)(g_z1 + (size_t)sn[k] * CH + lane * 4);
            d[k] = a.x * zc.x + a.y * zc.y + a.z * zc.z + a.w * zc.w;
        }
#pragma unroll
        for (int o = 16; o; o >>= 1) {
#pragma unroll
            for (int k = 0; k < 4; k++)
                d[k] += __shfl_xor_sync(0xffffffffu, d[k], o);
        }
        if (lane == 0) {
#pragma unroll
            for (int k = 0; k < 4; k++)
                g_sf[g_eid[j + k]] = 1.f / (1.f + __expf(-d[k]));
        }
    }
    for (; j < s1; j++) {
        int s = g_adj[j];
        const float4 a = *(const float4*)(g_z1 + (size_t)s * CH + lane * 4);
        float d = a.x * zc.x + a.y * zc.y + a.z * zc.z + a.w * zc.w;
#pragma unroll
        for (int o = 16; o; o >>= 1) d += __shfl_xor_sync(0xffffffffu, d, o);
        if (lane == 0) g_sf[g_eid[j]] = 1.f / (1.f + __expf(-d));
    }
}

__global__ __launch_bounds__(256) void fatD_kernel(
    const float* __restrict__ x2, const float* __restrict__ W22) {
    __shared__ float smem[SMEM_FLOATS];
    int b = blockIdx.x;
    bool isZ2 = (b < 1600) && (b % 4 == 0);
    if (isZ2) {
        z2_body4(x2, W22, 8400 + (b / 4) * 4, smem);
    } else {
        int zBefore = (b < 1600) ? ((b + 3) / 4) : 400;
        int g = b - zBefore;
        int node = g * 8 + (threadIdx.x >> 5);
        if (node < N_NODES) decf_body_warp(node);
    }
}

// ---------------- final: out = sf^2 + (1-sf)*sigmoid(z2c0[r]+z2c0[c]); reset state ----------------
__global__ __launch_bounds__(256) void final_kernel(float* __restrict__ out) {
    int e = blockIdx.x * blockDim.x + threadIdx.x;
    if (e < N_NODES) { g_cnt[e] = 0; g_pos[e] = 0; }
    if (e == 0) ct_cvt = 0;
    if (e >= N_EDGES) return;
    float sf = g_sf[e];
    float vn = g_z2c0[g_src[e]] + g_z2c0[g_tgt[e]];
    float sn = 1.f / (1.f + __expf(-vn));
    out[e] = sf * sf + (1.f - sf) * sn;
}

// ---------------- launch ----------------
extern "C" void kernel_launch(void* const* d_in, const int* in_sizes, int n_in,
                              void* d_out, int out_size) {
    const float* x    = (const float*)d_in[0];
    const float* x2   = (const float*)d_in[1];
    const float* W2   = (const float*)d_in[2];
    const float* b2   = (const float*)d_in[3];
    const float* Wg   = (const float*)d_in[4];
    const float* bg   = (const float*)d_in[5];
    const float* W22  = (const float*)d_in[6];
    const int*   edge = (const int*)d_in[7];
    float* out = (float*)d_out;

    fatA_kernel<<<GEMM_BLOCKS + AUX_BLOCKS + Z2A_BLK, 256>>>(x, W2, b2, edge, x2, W22);
    fatB_kernel<<<GEMM_BLOCKS + AUX_BLOCKS + Z2B_BLK, 256>>>(Wg, x2, W22);
    fatC_kernel<<<GATHER_BLOCKS + Z2C_BLK, 256>>>(bg, x2, W22);
    fatD_kernel<<<DECF_BLOCKS + Z2D_BLK, 256>>>(x2, W22);
    final_kernel<<<(N_EDGES + 255) / 256, 256>>>(out);
}

// round 15
// speedup vs baseline: 1.5415x; 1.0078x over previous
#include <cuda_runtime.h>
#include <stdint.h>
#include <math.h>

#define N_NODES 10000
#define N_EDGES 320000
#define IN_DIM  512
#define CH      128

// ---------------- scratch (device globals; zero-initialized at load) ----------------
__device__ float g_h  [N_NODES * CH];
__device__ float g_xw [N_NODES * CH];
__device__ float g_z1 [N_NODES * CH];
__device__ float g_dinv[N_NODES];
__device__ int   g_cnt [N_NODES];       // re-zeroed by final kernel each run
__device__ int   g_pos [N_NODES];       // re-zeroed by final kernel each run
__device__ int   g_off [N_NODES + 1];
__device__ int   g_src [N_EDGES];
__device__ int   g_tgt [N_EDGES];
__device__ int   g_adj [N_EDGES];
__device__ int   g_eid [N_EDGES];
__device__ float g_sf  [N_EDGES];       // sigmoid(value_feature), by original edge id
__device__ float g_z2c0[N_NODES];
__device__ int   ct_cvt;                // cvt completion counter (reset in final)

// z2: 4 rows per block; static slices across four fat kernels
#define Z2A_BLK 700    // rows [0, 2800)
#define Z2B_BLK 800    // rows [2800, 6000)
#define Z2C_BLK 600    // rows [6000, 8400)
#define Z2D_BLK 400    // rows [8400, 10000)

#define GEMM_BLOCKS 157
#define AUX_BLOCKS  64          // cvt_count role (fatA) / fill role (fatB)

// ---------------- edge conversion (role inside fatA) ----------------
__device__ __forceinline__ bool edges_are_i64(const int* p) {
    bool b = true;
#pragma unroll
    for (int i = 0; i < 8; i++) b = b && (p[2 * i + 1] == 0);
    return b;
}

__device__ __forceinline__ void cvt_count_body(const int* __restrict__ ep, int bb) {
    bool i64 = edges_are_i64(ep);
    for (int e = threadIdx.x + bb * 256; e < N_EDGES; e += AUX_BLOCKS * 256) {
        int s, t;
        if (i64) {
            const long long* p = (const long long*)ep;
            s = (int)p[e]; t = (int)p[N_EDGES + e];
        } else {
            s = ep[e]; t = ep[N_EDGES + e];
        }
        g_src[e] = s; g_tgt[e] = t;
        atomicAdd(&g_cnt[t], 1);
    }
}

// ---------------- scan body (256 threads): cnt -> off (exclusive), dinv ----------------
__device__ __forceinline__ void scan_body256(int* wsum) {
    int tid = threadIdx.x, lane = tid & 31, wid = tid >> 5;
    int carry = 0;
    for (int base = 0; base < N_NODES; base += 256) {
        int idx = base + tid;
        int v = (idx < N_NODES) ? g_cnt[idx] : 0;
        int x = v;
#pragma unroll
        for (int d = 1; d < 32; d <<= 1) {
            int y = __shfl_up_sync(0xffffffffu, x, d);
            if (lane >= d) x += y;
        }
        if (lane == 31) wsum[wid] = x;
        __syncthreads();
        if (wid == 0 && lane < 8) {
            int s = wsum[lane];
#pragma unroll
            for (int d = 1; d < 8; d <<= 1) {
                int y = __shfl_up_sync(0xffu, s, d);
                if (lane >= d) s += y;
            }
            wsum[lane] = s;
        }
        __syncthreads();
        int offset = wid ? wsum[wid - 1] : 0;
        if (idx < N_NODES) {
            g_off[idx] = carry + offset + x - v;
            g_dinv[idx] = rsqrtf((float)(v + 1));
        }
        carry += wsum[7];
        __syncthreads();
    }
    if (tid == 0) g_off[N_NODES] = carry;
}

// ---------------- tf32 MMA helpers ----------------
__device__ __forceinline__ unsigned f2tf32(float f) {
    unsigned u;
    asm("cvt.rna.tf32.f32 %0, %1;" : "=r"(u) : "f"(f));
    return u;
}

__device__ __forceinline__ void mma_tf32(float c[4], unsigned a0, unsigned a1,
                                         unsigned a2, unsigned a3,
                                         unsigned b0, unsigned b1) {
    asm volatile(
        "mma.sync.aligned.m16n8k8.row.col.f32.tf32.tf32.f32 "
        "{%0,%1,%2,%3}, {%4,%5,%6,%7}, {%8,%9}, {%0,%1,%2,%3};\n"
        : "+f"(c[0]), "+f"(c[1]), "+f"(c[2]), "+f"(c[3])
        : "r"(a0), "r"(a1), "r"(a2), "r"(a3), "r"(b0), "r"(b1));
}

#define WS_STRIDE 68
#define SMEM_FLOATS (128 * WS_STRIDE + 64)

// ---------------- tf32 GEMM block body: out[M,128] = A[M,K] @ W[128,K]^T ----------------
template <int KDIM, bool NORM, bool ROWSCALE>
__device__ __forceinline__ void gemm_tf32_body(
    const float* __restrict__ A, const float* __restrict__ W,
    const float* __restrict__ bias, const float* __restrict__ rs,
    float* __restrict__ out, int M, float scale, int m0, float* smem) {

    const int tid = threadIdx.x, lane = tid & 31, w = tid >> 5;
    const int gid = lane >> 2, tig = lane & 3;
    const int wm = w & 1, wn = w >> 1;
    const int mbase = m0 + wm * 32;
    const int nbase = wn * 32;
    float* Ws = smem;
    float* ssq = smem + 128 * WS_STRIDE;

    float acc[2][4][4];
#pragma unroll
    for (int i = 0; i < 2; i++)
#pragma unroll
        for (int j = 0; j < 4; j++)
#pragma unroll
            for (int q = 0; q < 4; q++) acc[i][j][q] = 0.f;

    bool vlo[2], vhi[2];
    int rlo[2], rhi[2];
#pragma unroll
    for (int i = 0; i < 2; i++) {
        rlo[i] = mbase + i * 16 + gid;
        rhi[i] = rlo[i] + 8;
        vlo[i] = rlo[i] < M;
        vhi[i] = rhi[i] < M;
    }

    for (int kt = 0; kt < KDIM; kt += 64) {
        __syncthreads();
#pragma unroll
        for (int it = 0; it < 8; it++) {
            int idx = tid + it * 256;
            int n = idx >> 4, q = idx & 15;
            float4 v = *(const float4*)(W + (size_t)n * KDIM + kt + q * 4);
            *(float4*)&Ws[n * WS_STRIDE + q * 4] = v;
        }
        __syncthreads();
#pragma unroll
        for (int k8 = 0; k8 < 8; k8++) {
            int kg = kt + k8 * 8;
            unsigned af[2][4];
#pragma unroll
            for (int i = 0; i < 2; i++) {
                const float* Alo = A + (size_t)rlo[i] * KDIM + kg + tig;
                const float* Ahi = A + (size_t)rhi[i] * KDIM + kg + tig;
                float a0 = vlo[i] ? Alo[0] : 0.f;
                float a1 = vhi[i] ? Ahi[0] : 0.f;
                float a2 = vlo[i] ? Alo[4] : 0.f;
                float a3 = vhi[i] ? Ahi[4] : 0.f;
                af[i][0] = f2tf32(a0); af[i][1] = f2tf32(a1);
                af[i][2] = f2tf32(a2); af[i][3] = f2tf32(a3);
            }
#pragma unroll
            for (int j = 0; j < 4; j++) {
                int n = nbase + j * 8 + gid;
                unsigned b0 = f2tf32(Ws[n * WS_STRIDE + k8 * 8 + tig]);
                unsigned b1 = f2tf32(Ws[n * WS_STRIDE + k8 * 8 + tig + 4]);
#pragma unroll
                for (int i = 0; i < 2; i++)
                    mma_tf32(acc[i][j], af[i][0], af[i][1], af[i][2], af[i][3], b0, b1);
            }
        }
    }

    if (bias) {
#pragma unroll
        for (int j = 0; j < 4; j++) {
            int col = nbase + j * 8 + 2 * tig;
            float bv0 = bias[col], bv1 = bias[col + 1];
#pragma unroll
            for (int i = 0; i < 2; i++) {
                acc[i][j][0] += bv0; acc[i][j][1] += bv1;
                acc[i][j][2] += bv0; acc[i][j][3] += bv1;
            }
        }
    }

    float mul_lo[2], mul_hi[2];
#pragma unroll
    for (int i = 0; i < 2; i++) { mul_lo[i] = 1.f; mul_hi[i] = 1.f; }

    if (NORM) {
        __syncthreads();
        if (tid < 64) ssq[tid] = 0.f;
        __syncthreads();
#pragma unroll
        for (int i = 0; i < 2; i++) {
            float plo = 0.f, phi = 0.f;
#pragma unroll
            for (int j = 0; j < 4; j++) {
                plo += acc[i][j][0] * acc[i][j][0] + acc[i][j][1] * acc[i][j][1];
                phi += acc[i][j][2] * acc[i][j][2] + acc[i][j][3] * acc[i][j][3];
            }
            plo += __shfl_xor_sync(0xffffffffu, plo, 1);
            plo += __shfl_xor_sync(0xffffffffu, plo, 2);
            phi += __shfl_xor_sync(0xffffffffu, phi, 1);
            phi += __shfl_xor_sync(0xffffffffu, phi, 2);
            if (tig == 0) {
                atomicAdd(&ssq[wm * 32 + i * 16 + gid], plo);
                atomicAdd(&ssq[wm * 32 + i * 16 + gid + 8], phi);
            }
        }
        __syncthreads();
#pragma unroll
        for (int i = 0; i < 2; i++) {
            mul_lo[i] = scale / fmaxf(sqrtf(ssq[wm * 32 + i * 16 + gid]), 1e-12f);
            mul_hi[i] = scale / fmaxf(sqrtf(ssq[wm * 32 + i * 16 + gid + 8]), 1e-12f);
        }
    }
    if (ROWSCALE) {
#pragma unroll
        for (int i = 0; i < 2; i++) {
            if (vlo[i]) mul_lo[i] *= rs[rlo[i]];
            if (vhi[i]) mul_hi[i] *= rs[rhi[i]];
        }
    }

#pragma unroll
    for (int i = 0; i < 2; i++) {
#pragma unroll
        for (int j = 0; j < 4; j++) {
            int col = nbase + j * 8 + 2 * tig;
            if (vlo[i]) {
                float2 o = make_float2(acc[i][j][0] * mul_lo[i], acc[i][j][1] * mul_lo[i]);
                *(float2*)(out + (size_t)rlo[i] * CH + col) = o;
            }
            if (vhi[i]) {
                float2 o = make_float2(acc[i][j][2] * mul_hi[i], acc[i][j][3] * mul_hi[i]);
                *(float2*)(out + (size_t)rhi[i] * CH + col) = o;
            }
        }
    }
}

// ---------------- z2 body: 4 rows per block, depth-2 register-pipelined DRAM stream ----------------
__device__ __forceinline__ void z2_body4(const float* __restrict__ x2,
                                         const float* __restrict__ W22,
                                         int row0, float* smem) {
    const int tid = threadIdx.x, lane = tid & 31, wid = tid >> 5;
    const int NV = N_NODES / 4;   // 2500 float4 per row; 10 chunks of 256
    const float4* __restrict__ w0 = (const float4*)W22;
    const float4* __restrict__ w1 = (const float4*)(W22 + N_NODES);
    const float4* xr[4];
#pragma unroll
    for (int k = 0; k < 4; k++)
        xr[k] = (const float4*)(x2 + (size_t)(row0 + k) * N_NODES);

    float s0[4] = {0.f, 0.f, 0.f, 0.f}, s1[4] = {0.f, 0.f, 0.f, 0.f};
    float4 a[4], an[4], an2[4];

#pragma unroll
    for (int k = 0; k < 4; k++) a[k]  = xr[k][tid];
#pragma unroll
    for (int k = 0; k < 4; k++) an[k] = xr[k][256 + tid];

    int j = tid;
#pragma unroll
    for (int c = 0; c < 10; c++) {
        bool v = j < NV;
        int js = v ? j : 0;
        float4 b = w0[js], cc = w1[js];
        if (!v) { b = make_float4(0.f,0.f,0.f,0.f); cc = make_float4(0.f,0.f,0.f,0.f); }
        if (c < 8) {
            int jp = j + 512;
            int jps = (jp < NV) ? jp : 0;
#pragma unroll
            for (int k = 0; k < 4; k++) an2[k] = xr[k][jps];
        }
#pragma unroll
        for (int k = 0; k < 4; k++) {
            s0[k] += a[k].x * b.x  + a[k].y * b.y  + a[k].z * b.z  + a[k].w * b.w;
            s1[k] += a[k].x * cc.x + a[k].y * cc.y + a[k].z * cc.z + a[k].w * cc.w;
        }
#pragma unroll
        for (int k = 0; k < 4; k++) { a[k] = an[k]; an[k] = an2[k]; }
        j += 256;
    }

#pragma unroll
    for (int k = 0; k < 4; k++) {
#pragma unroll
        for (int d = 16; d; d >>= 1) {
            s0[k] += __shfl_xor_sync(0xffffffffu, s0[k], d);
            s1[k] += __shfl_xor_sync(0xffffffffu, s1[k], d);
        }
    }
    float* r0 = smem;        // [4][8]
    float* r1 = smem + 32;   // [4][8]
    if (lane == 0) {
#pragma unroll
        for (int k = 0; k < 4; k++) { r0[k * 8 + wid] = s0[k]; r1[k * 8 + wid] = s1[k]; }
    }
    __syncthreads();
    if (tid < 4) {
        float y0 = 0.f, y1 = 0.f;
#pragma unroll
        for (int q = 0; q < 8; q++) { y0 += r0[tid * 8 + q]; y1 += r1[tid * 8 + q]; }
        float n = fmaxf(sqrtf(y0 * y0 + y1 * y1), 1e-12f);
        g_z2c0[row0 + tid] = 0.8f * y0 / n;
    }
}

// ---------------- fatA: gemm1 + cvt_count(+scan by last finisher) + z2 rows [0, 2800) ----------------
__global__ __launch_bounds__(256) void fatA_kernel(
    const float* __restrict__ x, const float* __restrict__ W2,
    const float* __restrict__ b2, const int* __restrict__ edge,
    const float* __restrict__ x2, const float* __restrict__ W22) {
    __shared__ float smem[SMEM_FLOATS];
    __shared__ int s_last;
    int b = blockIdx.x;
    if (b < GEMM_BLOCKS) {
        gemm_tf32_body<IN_DIM, true, false>(x, W2, b2, nullptr, g_h,
                                            N_NODES, 1.8f, b * 64, smem);
    } else if (b < GEMM_BLOCKS + AUX_BLOCKS) {
        cvt_count_body(edge, b - GEMM_BLOCKS);
        __threadfence();
        __syncthreads();
        if (threadIdx.x == 0)
            s_last = (atomicAdd(&ct_cvt, 1) == AUX_BLOCKS - 1);
        __syncthreads();
        if (s_last) {
            __threadfence();                 // ensure we see all g_cnt updates
            scan_body256((int*)smem);        // hidden under concurrent z2 stream
        }
    } else {
        z2_body4(x2, W22, (b - GEMM_BLOCKS - AUX_BLOCKS) * 4, smem);
    }
}

// ---------------- fatB: gemm2 + CSR fill + z2 rows [2800, 6000) ----------------
__global__ __launch_bounds__(256) void fatB_kernel(
    const float* __restrict__ Wg,
    const float* __restrict__ x2, const float* __restrict__ W22) {
    __shared__ float smem[SMEM_FLOATS];
    int b = blockIdx.x;
    if (b < GEMM_BLOCKS) {
        gemm_tf32_body<CH, false, true>(g_h, Wg, nullptr, g_dinv, g_xw,
                                        N_NODES, 1.0f, b * 64, smem);
    } else if (b < GEMM_BLOCKS + AUX_BLOCKS) {
        int bb = b - GEMM_BLOCKS;
        for (int e = threadIdx.x + bb * 256; e < N_EDGES; e += AUX_BLOCKS * 256) {
            int t = g_tgt[e];
            int p = atomicAdd(&g_pos[t], 1);
            int w = g_off[t] + p;
            g_adj[w] = g_src[e];
            g_eid[w] = e;
        }
    } else {
        z2_body4(x2, W22, 2800 + (b - GEMM_BLOCKS - AUX_BLOCKS) * 4, smem);
    }
}

// ---------------- gather: warp per node, float4 per lane, 8-edge unroll ----------------
__device__ __forceinline__ void gather_body_warp(const float* __restrict__ bg,
                                                 int node) {
    int lane = threadIdx.x & 31;
    float4 acc = *(const float4*)(g_xw + (size_t)node * CH + lane * 4);
    int s0 = g_off[node], s1 = g_off[node + 1];
    int j = s0;
    for (; j + 8 <= s1; j += 8) {
        int aa[8];
#pragma unroll
        for (int k = 0; k < 8; k++) aa[k] = g_adj[j + k];
        float4 v[8];
#pragma unroll
        for (int k = 0; k < 8; k++)
            v[k] = *(const float4*)(g_xw + (size_t)aa[k] * CH + lane * 4);
#pragma unroll
        for (int k = 0; k < 8; k++) {
            acc.x += v[k].x; acc.y += v[k].y; acc.z += v[k].z; acc.w += v[k].w;
        }
    }
    for (; j + 4 <= s1; j += 4) {
        int a0 = g_adj[j], a1 = g_adj[j + 1], a2 = g_adj[j + 2], a3 = g_adj[j + 3];
        float4 v0 = *(const float4*)(g_xw + (size_t)a0 * CH + lane * 4);
        float4 v1 = *(const float4*)(g_xw + (size_t)a1 * CH + lane * 4);
        float4 v2 = *(const float4*)(g_xw + (size_t)a2 * CH + lane * 4);
        float4 v3 = *(const float4*)(g_xw + (size_t)a3 * CH + lane * 4);
        acc.x += (v0.x + v1.x) + (v2.x + v3.x);
        acc.y += (v0.y + v1.y) + (v2.y + v3.y);
        acc.z += (v0.z + v1.z) + (v2.z + v3.z);
        acc.w += (v0.w + v1.w) + (v2.w + v3.w);
    }
    for (; j < s1; j++) {
        float4 v = *(const float4*)(g_xw + (size_t)g_adj[j] * CH + lane * 4);
        acc.x += v.x; acc.y += v.y; acc.z += v.z; acc.w += v.w;
    }
    float di = g_dinv[node];
    float4 bgv = *(const float4*)(bg + lane * 4);
    float4 o;
    o.x = acc.x * di + bgv.x;
    o.y = acc.y * di + bgv.y;
    o.z = acc.z * di + bgv.z;
    o.w = acc.w * di + bgv.w;
    *(float4*)(g_z1 + (size_t)node * CH + lane * 4) = o;
}

// ---------------- fatC: interleaved gather (1250) + z2 rows [6000, 8400) (600) ----------------
#define GATHER_BLOCKS 1250
__global__ __launch_bounds__(256) void fatC_kernel(
    const float* __restrict__ bg,
    const float* __restrict__ x2, const float* __restrict__ W22) {
    __shared__ float smem[SMEM_FLOATS];
    int b = blockIdx.x;
    bool isZ2 = (b < 1800) && (b % 3 == 0);
    if (isZ2) {
        z2_body4(x2, W22, 6000 + (b / 3) * 4, smem);
    } else {
        int zBefore = (b < 1800) ? ((b + 2) / 3) : 600;
        int g = b - zBefore;
        int node = g * 8 + (threadIdx.x >> 5);
        if (node < N_NODES) gather_body_warp(bg, node);
    }
}

// ---------------- decf: warp per node, 8-edge unroll ----------------
__device__ __forceinline__ void decf_body_warp(int node) {
    int lane = threadIdx.x & 31;
    float4 zc = *(const float4*)(g_z1 + (size_t)node * CH + lane * 4);
    int s0 = g_off[node], s1 = g_off[node + 1];
    int j = s0;
    for (; j + 8 <= s1; j += 8) {
        int sn[8]; float d[8];
#pragma unroll
        for (int k = 0; k < 8; k++) sn[k] = g_adj[j + k];
#pragma unroll
        for (int k = 0; k < 8; k++) {
            const float4 a = *(const float4*)(g_z1 + (size_t)sn[k] * CH + lane * 4);
            d[k] = a.x * zc.x + a.y * zc.y + a.z * zc.z + a.w * zc.w;
        }
#pragma unroll
        for (int o = 16; o; o >>= 1) {
#pragma unroll
            for (int k = 0; k < 8; k++)
                d[k] += __shfl_xor_sync(0xffffffffu, d[k], o);
        }
        if (lane == 0) {
#pragma unroll
            for (int k = 0; k < 8; k++)
                g_sf[g_eid[j + k]] = 1.f / (1.f + __expf(-d[k]));
        }
    }
    for (; j + 4 <= s1; j += 4) {
        int sn[4]; float d[4];
#pragma unroll
        for (int k = 0; k < 4; k++) sn[k] = g_adj[j + k];
#pragma unroll
        for (int k = 0; k < 4; k++) {
            const float4 a = *(const float4*)(g_z1 + (size_t)sn[k] * CH + lane * 4);
            d[k] = a.x * zc.x + a.y * zc.y + a.z * zc.z + a.w * zc.w;
        }
#pragma unroll
        for (int o = 16; o; o >>= 1) {
#pragma unroll
            for (int k = 0; k < 4; k++)
                d[k] += __shfl_xor_sync(0xffffffffu, d[k], o);
        }
        if (lane == 0) {
#pragma unroll
            for (int k = 0; k < 4; k++)
                g_sf[g_eid[j + k]] = 1.f / (1.f + __expf(-d[k]));
        }
    }
    for (; j < s1; j++) {
        int s = g_adj[j];
        const float4 a = *(const float4*)(g_z1 + (size_t)s * CH + lane * 4);
        float d = a.x * zc.x + a.y * zc.y + a.z * zc.z + a.w * zc.w;
#pragma unroll
        for (int o = 16; o; o >>= 1) d += __shfl_xor_sync(0xffffffffu, d, o);
        if (lane == 0) g_sf[g_eid[j]] = 1.f / (1.f + __expf(-d));
    }
}

// ---------------- fatD: interleaved decf (1250) + z2 rows [8400, 10000) (400) ----------------
#define DECF_BLOCKS 1250
__global__ __launch_bounds__(256) void fatD_kernel(
    const float* __restrict__ x2, const float* __restrict__ W22) {
    __shared__ float smem[SMEM_FLOATS];
    int b = blockIdx.x;
    bool isZ2 = (b < 1600) && (b % 4 == 0);
    if (isZ2) {
        z2_body4(x2, W22, 8400 + (b / 4) * 4, smem);
    } else {
        int zBefore = (b < 1600) ? ((b + 3) / 4) : 400;
        int g = b - zBefore;
        int node = g * 8 + (threadIdx.x >> 5);
        if (node < N_NODES) decf_body_warp(node);
    }
}

// ---------------- final: out = sf^2 + (1-sf)*sigmoid(z2c0[r]+z2c0[c]); reset state ----------------
__global__ __launch_bounds__(256) void final_kernel(float* __restrict__ out) {
    int e = blockIdx.x * blockDim.x + threadIdx.x;
    if (e < N_NODES) { g_cnt[e] = 0; g_pos[e] = 0; }
    if (e == 0) ct_cvt = 0;
    if (e >= N_EDGES) return;
    float sf = g_sf[e];
    float vn = g_z2c0[g_src[e]] + g_z2c0[g_tgt[e]];
    float sn = 1.f / (1.f + __expf(-vn));
    out[e] = sf * sf + (1.f - sf) * sn;
}

// ---------------- launch ----------------
extern "C" void kernel_launch(void* const* d_in, const int* in_sizes, int n_in,
                              void* d_out, int out_size) {
    const float* x    = (const float*)d_in[0];
    const float* x2   = (const float*)d_in[1];
    const float* W2   = (const float*)d_in[2];
    const float* b2   = (const float*)d_in[3];
    const float* Wg   = (const float*)d_in[4];
    const float* bg   = (const float*)d_in[5];
    const float* W22  = (const float*)d_in[6];
    const int*   edge = (const int*)d_in[7];
    float* out = (float*)d_out;

    fatA_kernel<<<GEMM_BLOCKS + AUX_BLOCKS + Z2A_BLK, 256>>>(x, W2, b2, edge, x2, W22);
    fatB_kernel<<<GEMM_BLOCKS + AUX_BLOCKS + Z2B_BLK, 256>>>(Wg, x2, W22);
    fatC_kernel<<<GATHER_BLOCKS + Z2C_BLK, 256>>>(bg, x2, W22);
    fatD_kernel<<<DECF_BLOCKS + Z2D_BLK, 256>>>(x2, W22);
    final_kernel<<<(N_EDGES + 255) / 256, 256>>>(out);
}

// round 16
// speedup vs baseline: 1.5428x; 1.0008x over previous
#include <cuda_runtime.h>
#include <stdint.h>
#include <math.h>

#define N_NODES 10000
#define N_EDGES 320000
#define IN_DIM  512
#define CH      128

// ---------------- scratch (device globals; zero-initialized at load) ----------------
__device__ float g_h  [N_NODES * CH];
__device__ float g_xw [N_NODES * CH];
__device__ float g_z1 [N_NODES * CH];
__device__ float g_dinv[N_NODES];
__device__ int   g_cnt [N_NODES];       // re-zeroed by final kernel each run
__device__ int   g_pos [N_NODES];       // re-zeroed by final kernel each run
__device__ int   g_off [N_NODES + 1];
__device__ int   g_src [N_EDGES];
__device__ int   g_tgt [N_EDGES];
__device__ int   g_adj [N_EDGES];
__device__ int   g_eid [N_EDGES];
__device__ float g_sf  [N_EDGES];       // sigmoid(value_feature), by original edge id
__device__ float g_z2c0[N_NODES];
__device__ int   ct_cvt;                // cvt completion counter (reset in final)

// z2: 4 rows per block; static slices across four fat kernels
#define Z2A_BLK 700    // rows [0, 2800)
#define Z2B_BLK 800    // rows [2800, 6000)
#define Z2C_BLK 600    // rows [6000, 8400)
#define Z2D_BLK 400    // rows [8400, 10000)

#define GEMM_BLOCKS 157
#define AUX_BLOCKS  64          // cvt_count role (fatA) / fill role (fatB)

// ---------------- edge conversion (role inside fatA) ----------------
__device__ __forceinline__ bool edges_are_i64(const int* p) {
    bool b = true;
#pragma unroll
    for (int i = 0; i < 8; i++) b = b && (p[2 * i + 1] == 0);
    return b;
}

__device__ __forceinline__ void cvt_count_body(const int* __restrict__ ep, int bb) {
    bool i64 = edges_are_i64(ep);
    for (int e = threadIdx.x + bb * 256; e < N_EDGES; e += AUX_BLOCKS * 256) {
        int s, t;
        if (i64) {
            const long long* p = (const long long*)ep;
            s = (int)p[e]; t = (int)p[N_EDGES + e];
        } else {
            s = ep[e]; t = ep[N_EDGES + e];
        }
        g_src[e] = s; g_tgt[e] = t;
        atomicAdd(&g_cnt[t], 1);
    }
}

// ---------------- scan body (256 threads): cnt -> off (exclusive), dinv ----------------
__device__ __forceinline__ void scan_body256(int* wsum) {
    int tid = threadIdx.x, lane = tid & 31, wid = tid >> 5;
    int carry = 0;
    for (int base = 0; base < N_NODES; base += 256) {
        int idx = base + tid;
        int v = (idx < N_NODES) ? g_cnt[idx] : 0;
        int x = v;
#pragma unroll
        for (int d = 1; d < 32; d <<= 1) {
            int y = __shfl_up_sync(0xffffffffu, x, d);
            if (lane >= d) x += y;
        }
        if (lane == 31) wsum[wid] = x;
        __syncthreads();
        if (wid == 0 && lane < 8) {
            int s = wsum[lane];
#pragma unroll
            for (int d = 1; d < 8; d <<= 1) {
                int y = __shfl_up_sync(0xffu, s, d);
                if (lane >= d) s += y;
            }
            wsum[lane] = s;
        }
        __syncthreads();
        int offset = wid ? wsum[wid - 1] : 0;
        if (idx < N_NODES) {
            g_off[idx] = carry + offset + x - v;
            g_dinv[idx] = rsqrtf((float)(v + 1));
        }
        carry += wsum[7];
        __syncthreads();
    }
    if (tid == 0) g_off[N_NODES] = carry;
}

// ---------------- tf32 MMA helpers ----------------
__device__ __forceinline__ unsigned f2tf32(float f) {
    unsigned u;
    asm("cvt.rna.tf32.f32 %0, %1;" : "=r"(u) : "f"(f));
    return u;
}

__device__ __forceinline__ void mma_tf32(float c[4], unsigned a0, unsigned a1,
                                         unsigned a2, unsigned a3,
                                         unsigned b0, unsigned b1) {
    asm volatile(
        "mma.sync.aligned.m16n8k8.row.col.f32.tf32.tf32.f32 "
        "{%0,%1,%2,%3}, {%4,%5,%6,%7}, {%8,%9}, {%0,%1,%2,%3};\n"
        : "+f"(c[0]), "+f"(c[1]), "+f"(c[2]), "+f"(c[3])
        : "r"(a0), "r"(a1), "r"(a2), "r"(a3), "r"(b0), "r"(b1));
}

#define WS_STRIDE 68
#define SMEM_FLOATS (128 * WS_STRIDE + 64)

// ---------------- tf32 GEMM block body: out[M,128] = A[M,K] @ W[128,K]^T ----------------
template <int KDIM, bool NORM, bool ROWSCALE>
__device__ __forceinline__ void gemm_tf32_body(
    const float* __restrict__ A, const float* __restrict__ W,
    const float* __restrict__ bias, const float* __restrict__ rs,
    float* __restrict__ out, int M, float scale, int m0, float* smem) {

    const int tid = threadIdx.x, lane = tid & 31, w = tid >> 5;
    const int gid = lane >> 2, tig = lane & 3;
    const int wm = w & 1, wn = w >> 1;
    const int mbase = m0 + wm * 32;
    const int nbase = wn * 32;
    float* Ws = smem;
    float* ssq = smem + 128 * WS_STRIDE;

    float acc[2][4][4];
#pragma unroll
    for (int i = 0; i < 2; i++)
#pragma unroll
        for (int j = 0; j < 4; j++)
#pragma unroll
            for (int q = 0; q < 4; q++) acc[i][j][q] = 0.f;

    bool vlo[2], vhi[2];
    int rlo[2], rhi[2];
#pragma unroll
    for (int i = 0; i < 2; i++) {
        rlo[i] = mbase + i * 16 + gid;
        rhi[i] = rlo[i] + 8;
        vlo[i] = rlo[i] < M;
        vhi[i] = rhi[i] < M;
    }

    for (int kt = 0; kt < KDIM; kt += 64) {
        __syncthreads();
#pragma unroll
        for (int it = 0; it < 8; it++) {
            int idx = tid + it * 256;
            int n = idx >> 4, q = idx & 15;
            float4 v = *(const float4*)(W + (size_t)n * KDIM + kt + q * 4);
            *(float4*)&Ws[n * WS_STRIDE + q * 4] = v;
        }
        __syncthreads();
#pragma unroll
        for (int k8 = 0; k8 < 8; k8++) {
            int kg = kt + k8 * 8;
            unsigned af[2][4];
#pragma unroll
            for (int i = 0; i < 2; i++) {
                const float* Alo = A + (size_t)rlo[i] * KDIM + kg + tig;
                const float* Ahi = A + (size_t)rhi[i] * KDIM + kg + tig;
                float a0 = vlo[i] ? Alo[0] : 0.f;
                float a1 = vhi[i] ? Ahi[0] : 0.f;
                float a2 = vlo[i] ? Alo[4] : 0.f;
                float a3 = vhi[i] ? Ahi[4] : 0.f;
                af[i][0] = f2tf32(a0); af[i][1] = f2tf32(a1);
                af[i][2] = f2tf32(a2); af[i][3] = f2tf32(a3);
            }
#pragma unroll
            for (int j = 0; j < 4; j++) {
                int n = nbase + j * 8 + gid;
                unsigned b0 = f2tf32(Ws[n * WS_STRIDE + k8 * 8 + tig]);
                unsigned b1 = f2tf32(Ws[n * WS_STRIDE + k8 * 8 + tig + 4]);
#pragma unroll
                for (int i = 0; i < 2; i++)
                    mma_tf32(acc[i][j], af[i][0], af[i][1], af[i][2], af[i][3], b0, b1);
            }
        }
    }

    if (bias) {
#pragma unroll
        for (int j = 0; j < 4; j++) {
            int col = nbase + j * 8 + 2 * tig;
            float bv0 = bias[col], bv1 = bias[col + 1];
#pragma unroll
            for (int i = 0; i < 2; i++) {
                acc[i][j][0] += bv0; acc[i][j][1] += bv1;
                acc[i][j][2] += bv0; acc[i][j][3] += bv1;
            }
        }
    }

    float mul_lo[2], mul_hi[2];
#pragma unroll
    for (int i = 0; i < 2; i++) { mul_lo[i] = 1.f; mul_hi[i] = 1.f; }

    if (NORM) {
        __syncthreads();
        if (tid < 64) ssq[tid] = 0.f;
        __syncthreads();
#pragma unroll
        for (int i = 0; i < 2; i++) {
            float plo = 0.f, phi = 0.f;
#pragma unroll
            for (int j = 0; j < 4; j++) {
                plo += acc[i][j][0] * acc[i][j][0] + acc[i][j][1] * acc[i][j][1];
                phi += acc[i][j][2] * acc[i][j][2] + acc[i][j][3] * acc[i][j][3];
            }
            plo += __shfl_xor_sync(0xffffffffu, plo, 1);
            plo += __shfl_xor_sync(0xffffffffu, plo, 2);
            phi += __shfl_xor_sync(0xffffffffu, phi, 1);
            phi += __shfl_xor_sync(0xffffffffu, phi, 2);
            if (tig == 0) {
                atomicAdd(&ssq[wm * 32 + i * 16 + gid], plo);
                atomicAdd(&ssq[wm * 32 + i * 16 + gid + 8], phi);
            }
        }
        __syncthreads();
#pragma unroll
        for (int i = 0; i < 2; i++) {
            mul_lo[i] = scale / fmaxf(sqrtf(ssq[wm * 32 + i * 16 + gid]), 1e-12f);
            mul_hi[i] = scale / fmaxf(sqrtf(ssq[wm * 32 + i * 16 + gid + 8]), 1e-12f);
        }
    }
    if (ROWSCALE) {
#pragma unroll
        for (int i = 0; i < 2; i++) {
            if (vlo[i]) mul_lo[i] *= rs[rlo[i]];
            if (vhi[i]) mul_hi[i] *= rs[rhi[i]];
        }
    }

#pragma unroll
    for (int i = 0; i < 2; i++) {
#pragma unroll
        for (int j = 0; j < 4; j++) {
            int col = nbase + j * 8 + 2 * tig;
            if (vlo[i]) {
                float2 o = make_float2(acc[i][j][0] * mul_lo[i], acc[i][j][1] * mul_lo[i]);
                *(float2*)(out + (size_t)rlo[i] * CH + col) = o;
            }
            if (vhi[i]) {
                float2 o = make_float2(acc[i][j][2] * mul_hi[i], acc[i][j][3] * mul_hi[i]);
                *(float2*)(out + (size_t)rhi[i] * CH + col) = o;
            }
        }
    }
}

// ---------------- z2 body: 4 rows per block, depth-2 register-pipelined DRAM stream ----------------
__device__ __forceinline__ void z2_body4(const float* __restrict__ x2,
                                         const float* __restrict__ W22,
                                         int row0, float* smem) {
    const int tid = threadIdx.x, lane = tid & 31, wid = tid >> 5;
    const int NV = N_NODES / 4;   // 2500 float4 per row; 10 chunks of 256
    const float4* __restrict__ w0 = (const float4*)W22;
    const float4* __restrict__ w1 = (const float4*)(W22 + N_NODES);
    const float4* xr[4];
#pragma unroll
    for (int k = 0; k < 4; k++)
        xr[k] = (const float4*)(x2 + (size_t)(row0 + k) * N_NODES);

    float s0[4] = {0.f, 0.f, 0.f, 0.f}, s1[4] = {0.f, 0.f, 0.f, 0.f};
    float4 a[4], an[4], an2[4];

#pragma unroll
    for (int k = 0; k < 4; k++) a[k]  = xr[k][tid];
#pragma unroll
    for (int k = 0; k < 4; k++) an[k] = xr[k][256 + tid];

    int j = tid;
#pragma unroll
    for (int c = 0; c < 10; c++) {
        bool v = j < NV;
        int js = v ? j : 0;
        float4 b = w0[js], cc = w1[js];
        if (!v) { b = make_float4(0.f,0.f,0.f,0.f); cc = make_float4(0.f,0.f,0.f,0.f); }
        if (c < 8) {
            int jp = j + 512;
            int jps = (jp < NV) ? jp : 0;
#pragma unroll
            for (int k = 0; k < 4; k++) an2[k] = xr[k][jps];
        }
#pragma unroll
        for (int k = 0; k < 4; k++) {
            s0[k] += a[k].x * b.x  + a[k].y * b.y  + a[k].z * b.z  + a[k].w * b.w;
            s1[k] += a[k].x * cc.x + a[k].y * cc.y + a[k].z * cc.z + a[k].w * cc.w;
        }
#pragma unroll
        for (int k = 0; k < 4; k++) { a[k] = an[k]; an[k] = an2[k]; }
        j += 256;
    }

#pragma unroll
    for (int k = 0; k < 4; k++) {
#pragma unroll
        for (int d = 16; d; d >>= 1) {
            s0[k] += __shfl_xor_sync(0xffffffffu, s0[k], d);
            s1[k] += __shfl_xor_sync(0xffffffffu, s1[k], d);
        }
    }
    float* r0 = smem;        // [4][8]
    float* r1 = smem + 32;   // [4][8]
    if (lane == 0) {
#pragma unroll
        for (int k = 0; k < 4; k++) { r0[k * 8 + wid] = s0[k]; r1[k * 8 + wid] = s1[k]; }
    }
    __syncthreads();
    if (tid < 4) {
        float y0 = 0.f, y1 = 0.f;
#pragma unroll
        for (int q = 0; q < 8; q++) { y0 += r0[tid * 8 + q]; y1 += r1[tid * 8 + q]; }
        float n = fmaxf(sqrtf(y0 * y0 + y1 * y1), 1e-12f);
        g_z2c0[row0 + tid] = 0.8f * y0 / n;
    }
}

// ---------------- fatA: gemm1 + cvt_count(+scan by last finisher) + z2 rows [0, 2800) ----------------
__global__ __launch_bounds__(256) void fatA_kernel(
    const float* __restrict__ x, const float* __restrict__ W2,
    const float* __restrict__ b2, const int* __restrict__ edge,
    const float* __restrict__ x2, const float* __restrict__ W22) {
    __shared__ float smem[SMEM_FLOATS];
    __shared__ int s_last;
    int b = blockIdx.x;
    if (b < GEMM_BLOCKS) {
        gemm_tf32_body<IN_DIM, true, false>(x, W2, b2, nullptr, g_h,
                                            N_NODES, 1.8f, b * 64, smem);
    } else if (b < GEMM_BLOCKS + AUX_BLOCKS) {
        cvt_count_body(edge, b - GEMM_BLOCKS);
        __threadfence();
        __syncthreads();
        if (threadIdx.x == 0)
            s_last = (atomicAdd(&ct_cvt, 1) == AUX_BLOCKS - 1);
        __syncthreads();
        if (s_last) {
            __threadfence();                 // ensure we see all g_cnt updates
            scan_body256((int*)smem);        // hidden under concurrent z2 stream
        }
    } else {
        z2_body4(x2, W22, (b - GEMM_BLOCKS - AUX_BLOCKS) * 4, smem);
    }
}

// ---------------- fatB: gemm2 + CSR fill + z2 rows [2800, 6000) ----------------
__global__ __launch_bounds__(256) void fatB_kernel(
    const float* __restrict__ Wg,
    const float* __restrict__ x2, const float* __restrict__ W22) {
    __shared__ float smem[SMEM_FLOATS];
    int b = blockIdx.x;
    if (b < GEMM_BLOCKS) {
        gemm_tf32_body<CH, false, true>(g_h, Wg, nullptr, g_dinv, g_xw,
                                        N_NODES, 1.0f, b * 64, smem);
    } else if (b < GEMM_BLOCKS + AUX_BLOCKS) {
        int bb = b - GEMM_BLOCKS;
        for (int e = threadIdx.x + bb * 256; e < N_EDGES; e += AUX_BLOCKS * 256) {
            int t = g_tgt[e];
            int p = atomicAdd(&g_pos[t], 1);
            int w = g_off[t] + p;
            g_adj[w] = g_src[e];
            g_eid[w] = e;
        }
    } else {
        z2_body4(x2, W22, 2800 + (b - GEMM_BLOCKS - AUX_BLOCKS) * 4, smem);
    }
}

// ---------------- gather: warp per node, float4 per lane, 8-edge unroll ----------------
__device__ __forceinline__ void gather_body_warp(const float* __restrict__ bg,
                                                 int node) {
    int lane = threadIdx.x & 31;
    float4 acc = *(const float4*)(g_xw + (size_t)node * CH + lane * 4);
    int s0 = g_off[node], s1 = g_off[node + 1];
    int j = s0;
    for (; j + 8 <= s1; j += 8) {
        int aa[8];
#pragma unroll
        for (int k = 0; k < 8; k++) aa[k] = g_adj[j + k];
        float4 v[8];
#pragma unroll
        for (int k = 0; k < 8; k++)
            v[k] = *(const float4*)(g_xw + (size_t)aa[k] * CH + lane * 4);
#pragma unroll
        for (int k = 0; k < 8; k++) {
            acc.x += v[k].x; acc.y += v[k].y; acc.z += v[k].z; acc.w += v[k].w;
        }
    }
    for (; j + 4 <= s1; j += 4) {
        int a0 = g_adj[j], a1 = g_adj[j + 1], a2 = g_adj[j + 2], a3 = g_adj[j + 3];
        float4 v0 = *(const float4*)(g_xw + (size_t)a0 * CH + lane * 4);
        float4 v1 = *(const float4*)(g_xw + (size_t)a1 * CH + lane * 4);
        float4 v2 = *(const float4*)(g_xw + (size_t)a2 * CH + lane * 4);
        float4 v3 = *(const float4*)(g_xw + (size_t)a3 * CH + lane * 4);
        acc.x += (v0.x + v1.x) + (v2.x + v3.x);
        acc.y += (v0.y + v1.y) + (v2.y + v3.y);
        acc.z += (v0.z + v1.z) + (v2.z + v3.z);
        acc.w += (v0.w + v1.w) + (v2.w + v3.w);
    }
    for (; j < s1; j++) {
        float4 v = *(const float4*)(g_xw + (size_t)g_adj[j] * CH + lane * 4);
        acc.x += v.x; acc.y += v.y; acc.z += v.z; acc.w += v.w;
    }
    float di = g_dinv[node];
    float4 bgv = *(const float4*)(bg + lane * 4);
    float4 o;
    o.x = acc.x * di + bgv.x;
    o.y = acc.y * di + bgv.y;
    o.z = acc.z * di + bgv.z;
    o.w = acc.w * di + bgv.w;
    *(float4*)(g_z1 + (size_t)node * CH + lane * 4) = o;
}

// ---------------- fatC: interleaved gather (1250) + z2 rows [6000, 8400) (600) ----------------
#define GATHER_BLOCKS 1250
__global__ __launch_bounds__(256) void fatC_kernel(
    const float* __restrict__ bg,
    const float* __restrict__ x2, const float* __restrict__ W22) {
    __shared__ float smem[SMEM_FLOATS];
    int b = blockIdx.x;
    bool isZ2 = (b < 1800) && (b % 3 == 0);
    if (isZ2) {
        z2_body4(x2, W22, 6000 + (b / 3) * 4, smem);
    } else {
        int zBefore = (b < 1800) ? ((b + 2) / 3) : 600;
        int g = b - zBefore;
        int node = g * 8 + (threadIdx.x >> 5);
        if (node < N_NODES) gather_body_warp(bg, node);
    }
}

// ---------------- decf: 16 lanes per edge, 2 edges per warp concurrently ----------------
// Each lane covers 8 channels of its half-warp's edge; 4-step butterfly; each
// SHFL serves two edges at once -> 16 SHFL per 8 edges (was 40).
__device__ __forceinline__ void decf_body_warp(int node) {
    int lane = threadIdx.x & 31;
    int half = lane >> 4;       // 0: even-slot edge, 1: odd-slot edge
    int hl = lane & 15;         // lane within half
    const float* zcp = g_z1 + (size_t)node * CH + hl * 8;
    float4 zc0 = *(const float4*)zcp;
    float4 zc1 = *(const float4*)(zcp + 4);
    int s0 = g_off[node], s1 = g_off[node + 1];
    int j = s0;
    for (; j + 8 <= s1; j += 8) {
        int sn[4]; float d[4];
#pragma unroll
        for (int k = 0; k < 4; k++) sn[k] = g_adj[j + k * 2 + half];
#pragma unroll
        for (int k = 0; k < 4; k++) {
            const float* zp = g_z1 + (size_t)sn[k] * CH + hl * 8;
            float4 a0 = *(const float4*)zp;
            float4 a1 = *(const float4*)(zp + 4);
            d[k] = a0.x * zc0.x + a0.y * zc0.y + a0.z * zc0.z + a0.w * zc0.w
                 + a1.x * zc1.x + a1.y * zc1.y + a1.z * zc1.z + a1.w * zc1.w;
        }
#pragma unroll
        for (int o = 8; o; o >>= 1) {
#pragma unroll
            for (int k = 0; k < 4; k++)
                d[k] += __shfl_xor_sync(0xffffffffu, d[k], o);
        }
        if (hl == 0) {
#pragma unroll
            for (int k = 0; k < 4; k++)
                g_sf[g_eid[j + k * 2 + half]] = 1.f / (1.f + __expf(-d[k]));
        }
    }
    // remainder: both halves compute the same edge; 4-step reduce; lane 0 writes
    for (; j < s1; j++) {
        int s = g_adj[j];
        const float* zp = g_z1 + (size_t)s * CH + hl * 8;
        float4 a0 = *(const float4*)zp;
        float4 a1 = *(const float4*)(zp + 4);
        float d = a0.x * zc0.x + a0.y * zc0.y + a0.z * zc0.z + a0.w * zc0.w
                + a1.x * zc1.x + a1.y * zc1.y + a1.z * zc1.z + a1.w * zc1.w;
#pragma unroll
        for (int o = 8; o; o >>= 1) d += __shfl_xor_sync(0xffffffffu, d, o);
        if (lane == 0) g_sf[g_eid[j]] = 1.f / (1.f + __expf(-d));
    }
}

// ---------------- fatD: interleaved decf (1250) + z2 rows [8400, 10000) (400) ----------------
#define DECF_BLOCKS 1250
__global__ __launch_bounds__(256) void fatD_kernel(
    const float* __restrict__ x2, const float* __restrict__ W22) {
    __shared__ float smem[SMEM_FLOATS];
    int b = blockIdx.x;
    bool isZ2 = (b < 1600) && (b % 4 == 0);
    if (isZ2) {
        z2_body4(x2, W22, 8400 + (b / 4) * 4, smem);
    } else {
        int zBefore = (b < 1600) ? ((b + 3) / 4) : 400;
        int g = b - zBefore;
        int node = g * 8 + (threadIdx.x >> 5);
        if (node < N_NODES) decf_body_warp(node);
    }
}

// ---------------- final: out = sf^2 + (1-sf)*sigmoid(z2c0[r]+z2c0[c]); reset state ----------------
__global__ __launch_bounds__(256) void final_kernel(float* __restrict__ out) {
    int e = blockIdx.x * blockDim.x + threadIdx.x;
    if (e < N_NODES) { g_cnt[e] = 0; g_pos[e] = 0; }
    if (e == 0) ct_cvt = 0;
    if (e >= N_EDGES) return;
    float sf = g_sf[e];
    float vn = g_z2c0[g_src[e]] + g_z2c0[g_tgt[e]];
    float sn = 1.f / (1.f + __expf(-vn));
    out[e] = sf * sf + (1.f - sf) * sn;
}

// ---------------- launch ----------------
extern "C" void kernel_launch(void* const* d_in, const int* in_sizes, int n_in,
                              void* d_out, int out_size) {
    const float* x    = (const float*)d_in[0];
    const float* x2   = (const float*)d_in[1];
    const float* W2   = (const float*)d_in[2];
    const float* b2   = (const float*)d_in[3];
    const float* Wg   = (const float*)d_in[4];
    const float* bg   = (const float*)d_in[5];
    const float* W22  = (const float*)d_in[6];
    const int*   edge = (const int*)d_in[7];
    float* out = (float*)d_out;

    fatA_kernel<<<GEMM_BLOCKS + AUX_BLOCKS + Z2A_BLK, 256>>>(x, W2, b2, edge, x2, W22);
    fatB_kernel<<<GEMM_BLOCKS + AUX_BLOCKS + Z2B_BLK, 256>>>(Wg, x2, W22);
    fatC_kernel<<<GATHER_BLOCKS + Z2C_BLK, 256>>>(bg, x2, W22);
    fatD_kernel<<<DECF_BLOCKS + Z2D_BLK, 256>>>(x2, W22);
    final_kernel<<<(N_EDGES + 255) / 256, 256>>>(out);
}

// round 17
// speedup vs baseline: 1.5662x; 1.0152x over previous
#include <cuda_runtime.h>
#include <cuda_fp16.h>
#include <stdint.h>
#include <math.h>

#define N_NODES 10000
#define N_EDGES 320000
#define IN_DIM  512
#define CH      128

// ---------------- scratch (device globals; zero-initialized at load) ----------------
__device__ float  g_h  [N_NODES * CH];
__device__ __half g_xw [N_NODES * CH];   // fp16: gather-side traffic halved
__device__ __half g_z1 [N_NODES * CH];   // fp16: decf-side traffic halved
__device__ float  g_dinv[N_NODES];
__device__ int    g_cnt [N_NODES];       // re-zeroed by final kernel each run
__device__ int    g_pos [N_NODES];       // re-zeroed by final kernel each run
__device__ int    g_off [N_NODES + 1];
__device__ int    g_src [N_EDGES];
__device__ int    g_tgt [N_EDGES];
__device__ int    g_adj [N_EDGES];
__device__ int    g_eid [N_EDGES];
__device__ float  g_sf  [N_EDGES];       // sigmoid(value_feature), by original edge id
__device__ float  g_z2c0[N_NODES];
__device__ int    ct_cvt;                // cvt completion counter (reset in final)

// z2: 4 rows per block; static slices across four fat kernels
#define Z2A_BLK 700    // rows [0, 2800)
#define Z2B_BLK 800    // rows [2800, 6000)
#define Z2C_BLK 600    // rows [6000, 8400)
#define Z2D_BLK 400    // rows [8400, 10000)

#define GEMM_BLOCKS 157
#define AUX_BLOCKS  64          // cvt_count role (fatA) / fill role (fatB)

// ---------------- edge conversion (role inside fatA) ----------------
__device__ __forceinline__ bool edges_are_i64(const int* p) {
    bool b = true;
#pragma unroll
    for (int i = 0; i < 8; i++) b = b && (p[2 * i + 1] == 0);
    return b;
}

__device__ __forceinline__ void cvt_count_body(const int* __restrict__ ep, int bb) {
    bool i64 = edges_are_i64(ep);
    for (int e = threadIdx.x + bb * 256; e < N_EDGES; e += AUX_BLOCKS * 256) {
        int s, t;
        if (i64) {
            const long long* p = (const long long*)ep;
            s = (int)p[e]; t = (int)p[N_EDGES + e];
        } else {
            s = ep[e]; t = ep[N_EDGES + e];
        }
        g_src[e] = s; g_tgt[e] = t;
        atomicAdd(&g_cnt[t], 1);
    }
}

// ---------------- scan body (256 threads): cnt -> off (exclusive), dinv ----------------
__device__ __forceinline__ void scan_body256(int* wsum) {
    int tid = threadIdx.x, lane = tid & 31, wid = tid >> 5;
    int carry = 0;
    for (int base = 0; base < N_NODES; base += 256) {
        int idx = base + tid;
        int v = (idx < N_NODES) ? g_cnt[idx] : 0;
        int x = v;
#pragma unroll
        for (int d = 1; d < 32; d <<= 1) {
            int y = __shfl_up_sync(0xffffffffu, x, d);
            if (lane >= d) x += y;
        }
        if (lane == 31) wsum[wid] = x;
        __syncthreads();
        if (wid == 0 && lane < 8) {
            int s = wsum[lane];
#pragma unroll
            for (int d = 1; d < 8; d <<= 1) {
                int y = __shfl_up_sync(0xffu, s, d);
                if (lane >= d) s += y;
            }
            wsum[lane] = s;
        }
        __syncthreads();
        int offset = wid ? wsum[wid - 1] : 0;
        if (idx < N_NODES) {
            g_off[idx] = carry + offset + x - v;
            g_dinv[idx] = rsqrtf((float)(v + 1));
        }
        carry += wsum[7];
        __syncthreads();
    }
    if (tid == 0) g_off[N_NODES] = carry;
}

// ---------------- tf32 MMA helpers ----------------
__device__ __forceinline__ unsigned f2tf32(float f) {
    unsigned u;
    asm("cvt.rna.tf32.f32 %0, %1;" : "=r"(u) : "f"(f));
    return u;
}

__device__ __forceinline__ void mma_tf32(float c[4], unsigned a0, unsigned a1,
                                         unsigned a2, unsigned a3,
                                         unsigned b0, unsigned b1) {
    asm volatile(
        "mma.sync.aligned.m16n8k8.row.col.f32.tf32.tf32.f32 "
        "{%0,%1,%2,%3}, {%4,%5,%6,%7}, {%8,%9}, {%0,%1,%2,%3};\n"
        : "+f"(c[0]), "+f"(c[1]), "+f"(c[2]), "+f"(c[3])
        : "r"(a0), "r"(a1), "r"(a2), "r"(a3), "r"(b0), "r"(b1));
}

#define WS_STRIDE 68
#define SMEM_FLOATS (128 * WS_STRIDE + 64)

// ---------------- tf32 GEMM block body: out[M,128] = A[M,K] @ W[128,K]^T ----------------
// HALFOUT: store results as __half into outh (used by gemm2 -> g_xw)
template <int KDIM, bool NORM, bool ROWSCALE, bool HALFOUT>
__device__ __forceinline__ void gemm_tf32_body(
    const float* __restrict__ A, const float* __restrict__ W,
    const float* __restrict__ bias, const float* __restrict__ rs,
    float* __restrict__ out, __half* __restrict__ outh,
    int M, float scale, int m0, float* smem) {

    const int tid = threadIdx.x, lane = tid & 31, w = tid >> 5;
    const int gid = lane >> 2, tig = lane & 3;
    const int wm = w & 1, wn = w >> 1;
    const int mbase = m0 + wm * 32;
    const int nbase = wn * 32;
    float* Ws = smem;
    float* ssq = smem + 128 * WS_STRIDE;

    float acc[2][4][4];
#pragma unroll
    for (int i = 0; i < 2; i++)
#pragma unroll
        for (int j = 0; j < 4; j++)
#pragma unroll
            for (int q = 0; q < 4; q++) acc[i][j][q] = 0.f;

    bool vlo[2], vhi[2];
    int rlo[2], rhi[2];
#pragma unroll
    for (int i = 0; i < 2; i++) {
        rlo[i] = mbase + i * 16 + gid;
        rhi[i] = rlo[i] + 8;
        vlo[i] = rlo[i] < M;
        vhi[i] = rhi[i] < M;
    }

    for (int kt = 0; kt < KDIM; kt += 64) {
        __syncthreads();
#pragma unroll
        for (int it = 0; it < 8; it++) {
            int idx = tid + it * 256;
            int n = idx >> 4, q = idx & 15;
            float4 v = *(const float4*)(W + (size_t)n * KDIM + kt + q * 4);
            *(float4*)&Ws[n * WS_STRIDE + q * 4] = v;
        }
        __syncthreads();
#pragma unroll
        for (int k8 = 0; k8 < 8; k8++) {
            int kg = kt + k8 * 8;
            unsigned af[2][4];
#pragma unroll
            for (int i = 0; i < 2; i++) {
                const float* Alo = A + (size_t)rlo[i] * KDIM + kg + tig;
                const float* Ahi = A + (size_t)rhi[i] * KDIM + kg + tig;
                float a0 = vlo[i] ? Alo[0] : 0.f;
                float a1 = vhi[i] ? Ahi[0] : 0.f;
                float a2 = vlo[i] ? Alo[4] : 0.f;
                float a3 = vhi[i] ? Ahi[4] : 0.f;
                af[i][0] = f2tf32(a0); af[i][1] = f2tf32(a1);
                af[i][2] = f2tf32(a2); af[i][3] = f2tf32(a3);
            }
#pragma unroll
            for (int j = 0; j < 4; j++) {
                int n = nbase + j * 8 + gid;
                unsigned b0 = f2tf32(Ws[n * WS_STRIDE + k8 * 8 + tig]);
                unsigned b1 = f2tf32(Ws[n * WS_STRIDE + k8 * 8 + tig + 4]);
#pragma unroll
                for (int i = 0; i < 2; i++)
                    mma_tf32(acc[i][j], af[i][0], af[i][1], af[i][2], af[i][3], b0, b1);
            }
        }
    }

    if (bias) {
#pragma unroll
        for (int j = 0; j < 4; j++) {
            int col = nbase + j * 8 + 2 * tig;
            float bv0 = bias[col], bv1 = bias[col + 1];
#pragma unroll
            for (int i = 0; i < 2; i++) {
                acc[i][j][0] += bv0; acc[i][j][1] += bv1;
                acc[i][j][2] += bv0; acc[i][j][3] += bv1;
            }
        }
    }

    float mul_lo[2], mul_hi[2];
#pragma unroll
    for (int i = 0; i < 2; i++) { mul_lo[i] = 1.f; mul_hi[i] = 1.f; }

    if (NORM) {
        __syncthreads();
        if (tid < 64) ssq[tid] = 0.f;
        __syncthreads();
#pragma unroll
        for (int i = 0; i < 2; i++) {
            float plo = 0.f, phi = 0.f;
#pragma unroll
            for (int j = 0; j < 4; j++) {
                plo += acc[i][j][0] * acc[i][j][0] + acc[i][j][1] * acc[i][j][1];
                phi += acc[i][j][2] * acc[i][j][2] + acc[i][j][3] * acc[i][j][3];
            }
            plo += __shfl_xor_sync(0xffffffffu, plo, 1);
            plo += __shfl_xor_sync(0xffffffffu, plo, 2);
            phi += __shfl_xor_sync(0xffffffffu, phi, 1);
            phi += __shfl_xor_sync(0xffffffffu, phi, 2);
            if (tig == 0) {
                atomicAdd(&ssq[wm * 32 + i * 16 + gid], plo);
                atomicAdd(&ssq[wm * 32 + i * 16 + gid + 8], phi);
            }
        }
        __syncthreads();
#pragma unroll
        for (int i = 0; i < 2; i++) {
            mul_lo[i] = scale / fmaxf(sqrtf(ssq[wm * 32 + i * 16 + gid]), 1e-12f);
            mul_hi[i] = scale / fmaxf(sqrtf(ssq[wm * 32 + i * 16 + gid + 8]), 1e-12f);
        }
    }
    if (ROWSCALE) {
#pragma unroll
        for (int i = 0; i < 2; i++) {
            if (vlo[i]) mul_lo[i] *= rs[rlo[i]];
            if (vhi[i]) mul_hi[i] *= rs[rhi[i]];
        }
    }

#pragma unroll
    for (int i = 0; i < 2; i++) {
#pragma unroll
        for (int j = 0; j < 4; j++) {
            int col = nbase + j * 8 + 2 * tig;
            if (HALFOUT) {
                if (vlo[i]) {
                    __half2 h = __float22half2_rn(make_float2(
                        acc[i][j][0] * mul_lo[i], acc[i][j][1] * mul_lo[i]));
                    *(__half2*)(outh + (size_t)rlo[i] * CH + col) = h;
                }
                if (vhi[i]) {
                    __half2 h = __float22half2_rn(make_float2(
                        acc[i][j][2] * mul_hi[i], acc[i][j][3] * mul_hi[i]));
                    *(__half2*)(outh + (size_t)rhi[i] * CH + col) = h;
                }
            } else {
                if (vlo[i]) {
                    float2 o = make_float2(acc[i][j][0] * mul_lo[i], acc[i][j][1] * mul_lo[i]);
                    *(float2*)(out + (size_t)rlo[i] * CH + col) = o;
                }
                if (vhi[i]) {
                    float2 o = make_float2(acc[i][j][2] * mul_hi[i], acc[i][j][3] * mul_hi[i]);
                    *(float2*)(out + (size_t)rhi[i] * CH + col) = o;
                }
            }
        }
    }
}

// ---------------- z2 body: 4 rows per block, depth-2 register-pipelined DRAM stream ----------------
__device__ __forceinline__ void z2_body4(const float* __restrict__ x2,
                                         const float* __restrict__ W22,
                                         int row0, float* smem) {
    const int tid = threadIdx.x, lane = tid & 31, wid = tid >> 5;
    const int NV = N_NODES / 4;   // 2500 float4 per row; 10 chunks of 256
    const float4* __restrict__ w0 = (const float4*)W22;
    const float4* __restrict__ w1 = (const float4*)(W22 + N_NODES);
    const float4* xr[4];
#pragma unroll
    for (int k = 0; k < 4; k++)
        xr[k] = (const float4*)(x2 + (size_t)(row0 + k) * N_NODES);

    float s0[4] = {0.f, 0.f, 0.f, 0.f}, s1[4] = {0.f, 0.f, 0.f, 0.f};
    float4 a[4], an[4], an2[4];

#pragma unroll
    for (int k = 0; k < 4; k++) a[k]  = xr[k][tid];
#pragma unroll
    for (int k = 0; k < 4; k++) an[k] = xr[k][256 + tid];

    int j = tid;
#pragma unroll
    for (int c = 0; c < 10; c++) {
        bool v = j < NV;
        int js = v ? j : 0;
        float4 b = w0[js], cc = w1[js];
        if (!v) { b = make_float4(0.f,0.f,0.f,0.f); cc = make_float4(0.f,0.f,0.f,0.f); }
        if (c < 8) {
            int jp = j + 512;
            int jps = (jp < NV) ? jp : 0;
#pragma unroll
            for (int k = 0; k < 4; k++) an2[k] = xr[k][jps];
        }
#pragma unroll
        for (int k = 0; k < 4; k++) {
            s0[k] += a[k].x * b.x  + a[k].y * b.y  + a[k].z * b.z  + a[k].w * b.w;
            s1[k] += a[k].x * cc.x + a[k].y * cc.y + a[k].z * cc.z + a[k].w * cc.w;
        }
#pragma unroll
        for (int k = 0; k < 4; k++) { a[k] = an[k]; an[k] = an2[k]; }
        j += 256;
    }

#pragma unroll
    for (int k = 0; k < 4; k++) {
#pragma unroll
        for (int d = 16; d; d >>= 1) {
            s0[k] += __shfl_xor_sync(0xffffffffu, s0[k], d);
            s1[k] += __shfl_xor_sync(0xffffffffu, s1[k], d);
        }
    }
    float* r0 = smem;        // [4][8]
    float* r1 = smem + 32;   // [4][8]
    if (lane == 0) {
#pragma unroll
        for (int k = 0; k < 4; k++) { r0[k * 8 + wid] = s0[k]; r1[k * 8 + wid] = s1[k]; }
    }
    __syncthreads();
    if (tid < 4) {
        float y0 = 0.f, y1 = 0.f;
#pragma unroll
        for (int q = 0; q < 8; q++) { y0 += r0[tid * 8 + q]; y1 += r1[tid * 8 + q]; }
        float n = fmaxf(sqrtf(y0 * y0 + y1 * y1), 1e-12f);
        g_z2c0[row0 + tid] = 0.8f * y0 / n;
    }
}

// ---------------- fatA: gemm1 + cvt_count(+scan by last finisher) + z2 rows [0, 2800) ----------------
__global__ __launch_bounds__(256) void fatA_kernel(
    const float* __restrict__ x, const float* __restrict__ W2,
    const float* __restrict__ b2, const int* __restrict__ edge,
    const float* __restrict__ x2, const float* __restrict__ W22) {
    __shared__ float smem[SMEM_FLOATS];
    __shared__ int s_last;
    int b = blockIdx.x;
    if (b < GEMM_BLOCKS) {
        gemm_tf32_body<IN_DIM, true, false, false>(x, W2, b2, nullptr, g_h, nullptr,
                                                   N_NODES, 1.8f, b * 64, smem);
    } else if (b < GEMM_BLOCKS + AUX_BLOCKS) {
        cvt_count_body(edge, b - GEMM_BLOCKS);
        __threadfence();
        __syncthreads();
        if (threadIdx.x == 0)
            s_last = (atomicAdd(&ct_cvt, 1) == AUX_BLOCKS - 1);
        __syncthreads();
        if (s_last) {
            __threadfence();                 // ensure we see all g_cnt updates
            scan_body256((int*)smem);        // hidden under concurrent z2 stream
        }
    } else {
        z2_body4(x2, W22, (b - GEMM_BLOCKS - AUX_BLOCKS) * 4, smem);
    }
}

// ---------------- fatB: gemm2 (half out) + CSR fill + z2 rows [2800, 6000) ----------------
__global__ __launch_bounds__(256) void fatB_kernel(
    const float* __restrict__ Wg,
    const float* __restrict__ x2, const float* __restrict__ W22) {
    __shared__ float smem[SMEM_FLOATS];
    int b = blockIdx.x;
    if (b < GEMM_BLOCKS) {
        gemm_tf32_body<CH, false, true, true>(g_h, Wg, nullptr, g_dinv, nullptr, g_xw,
                                              N_NODES, 1.0f, b * 64, smem);
    } else if (b < GEMM_BLOCKS + AUX_BLOCKS) {
        int bb = b - GEMM_BLOCKS;
        for (int e = threadIdx.x + bb * 256; e < N_EDGES; e += AUX_BLOCKS * 256) {
            int t = g_tgt[e];
            int p = atomicAdd(&g_pos[t], 1);
            int w = g_off[t] + p;
            g_adj[w] = g_src[e];
            g_eid[w] = e;
        }
    } else {
        z2_body4(x2, W22, 2800 + (b - GEMM_BLOCKS - AUX_BLOCKS) * 4, smem);
    }
}

// ---------------- gather: warp per node, 4 ch (uint2 of half2) per lane, 8-edge unroll ----------------
__device__ __forceinline__ void gather_body_warp(const float* __restrict__ bg,
                                                 int node) {
    int lane = threadIdx.x & 31;
    // accumulate in fp32
    float2 acc0, acc1;
    {
        uint2 v = *(const uint2*)(g_xw + (size_t)node * CH + lane * 4);
        acc0 = __half22float2(*(__half2*)&v.x);
        acc1 = __half22float2(*(__half2*)&v.y);
    }
    int s0 = g_off[node], s1 = g_off[node + 1];
    int j = s0;
    for (; j + 8 <= s1; j += 8) {
        int aa[8];
#pragma unroll
        for (int k = 0; k < 8; k++) aa[k] = g_adj[j + k];
        uint2 v[8];
#pragma unroll
        for (int k = 0; k < 8; k++)
            v[k] = *(const uint2*)(g_xw + (size_t)aa[k] * CH + lane * 4);
#pragma unroll
        for (int k = 0; k < 8; k++) {
            float2 f0 = __half22float2(*(__half2*)&v[k].x);
            float2 f1 = __half22float2(*(__half2*)&v[k].y);
            acc0.x += f0.x; acc0.y += f0.y;
            acc1.x += f1.x; acc1.y += f1.y;
        }
    }
    for (; j < s1; j++) {
        uint2 v = *(const uint2*)(g_xw + (size_t)g_adj[j] * CH + lane * 4);
        float2 f0 = __half22float2(*(__half2*)&v.x);
        float2 f1 = __half22float2(*(__half2*)&v.y);
        acc0.x += f0.x; acc0.y += f0.y;
        acc1.x += f1.x; acc1.y += f1.y;
    }
    float di = g_dinv[node];
    float4 bgv = *(const float4*)(bg + lane * 4);
    __half2 o0 = __float22half2_rn(make_float2(acc0.x * di + bgv.x, acc0.y * di + bgv.y));
    __half2 o1 = __float22half2_rn(make_float2(acc1.x * di + bgv.z, acc1.y * di + bgv.w));
    uint2 st;
    st.x = *(unsigned*)&o0; st.y = *(unsigned*)&o1;
    *(uint2*)(g_z1 + (size_t)node * CH + lane * 4) = st;
}

// ---------------- fatC: interleaved gather (1250) + z2 rows [6000, 8400) (600) ----------------
#define GATHER_BLOCKS 1250
__global__ __launch_bounds__(256) void fatC_kernel(
    const float* __restrict__ bg,
    const float* __restrict__ x2, const float* __restrict__ W22) {
    __shared__ float smem[SMEM_FLOATS];
    int b = blockIdx.x;
    bool isZ2 = (b < 1800) && (b % 3 == 0);
    if (isZ2) {
        z2_body4(x2, W22, 6000 + (b / 3) * 4, smem);
    } else {
        int zBefore = (b < 1800) ? ((b + 2) / 3) : 600;
        int g = b - zBefore;
        int node = g * 8 + (threadIdx.x >> 5);
        if (node < N_NODES) gather_body_warp(bg, node);
    }
}

// ---------------- decf: 16 lanes/edge, 2 edges/warp; 8 ch per lane = ONE uint4 load ----------------
__device__ __forceinline__ float dot8_half(uint4 a, uint4 z) {
    float2 a0 = __half22float2(*(__half2*)&a.x), z0 = __half22float2(*(__half2*)&z.x);
    float2 a1 = __half22float2(*(__half2*)&a.y), z1 = __half22float2(*(__half2*)&z.y);
    float2 a2 = __half22float2(*(__half2*)&a.z), z2 = __half22float2(*(__half2*)&z.z);
    float2 a3 = __half22float2(*(__half2*)&a.w), z3 = __half22float2(*(__half2*)&z.w);
    return a0.x * z0.x + a0.y * z0.y + a1.x * z1.x + a1.y * z1.y
         + a2.x * z2.x + a2.y * z2.y + a3.x * z3.x + a3.y * z3.y;
}

__device__ __forceinline__ void decf_body_warp(int node) {
    int lane = threadIdx.x & 31;
    int half = lane >> 4;       // 0: even-slot edge, 1: odd-slot edge
    int hl = lane & 15;         // lane within half
    uint4 zc = *(const uint4*)(g_z1 + (size_t)node * CH + hl * 8);
    int s0 = g_off[node], s1 = g_off[node + 1];
    int j = s0;
    for (; j + 8 <= s1; j += 8) {
        int sn[4]; float d[4];
#pragma unroll
        for (int k = 0; k < 4; k++) sn[k] = g_adj[j + k * 2 + half];
        uint4 av[4];
#pragma unroll
        for (int k = 0; k < 4; k++)
            av[k] = *(const uint4*)(g_z1 + (size_t)sn[k] * CH + hl * 8);
#pragma unroll
        for (int k = 0; k < 4; k++) d[k] = dot8_half(av[k], zc);
#pragma unroll
        for (int o = 8; o; o >>= 1) {
#pragma unroll
            for (int k = 0; k < 4; k++)
                d[k] += __shfl_xor_sync(0xffffffffu, d[k], o);
        }
        if (hl == 0) {
#pragma unroll
            for (int k = 0; k < 4; k++)
                g_sf[g_eid[j + k * 2 + half]] = 1.f / (1.f + __expf(-d[k]));
        }
    }
    // remainder: both halves compute the same edge; lane 0 writes
    for (; j < s1; j++) {
        int s = g_adj[j];
        uint4 a = *(const uint4*)(g_z1 + (size_t)s * CH + hl * 8);
        float d = dot8_half(a, zc);
#pragma unroll
        for (int o = 8; o; o >>= 1) d += __shfl_xor_sync(0xffffffffu, d, o);
        if (lane == 0) g_sf[g_eid[j]] = 1.f / (1.f + __expf(-d));
    }
}

// ---------------- fatD: interleaved decf (1250) + z2 rows [8400, 10000) (400) ----------------
#define DECF_BLOCKS 1250
__global__ __launch_bounds__(256) void fatD_kernel(
    const float* __restrict__ x2, const float* __restrict__ W22) {
    __shared__ float smem[SMEM_FLOATS];
    int b = blockIdx.x;
    bool isZ2 = (b < 1600) && (b % 4 == 0);
    if (isZ2) {
        z2_body4(x2, W22, 8400 + (b / 4) * 4, smem);
    } else {
        int zBefore = (b < 1600) ? ((b + 3) / 4) : 400;
        int g = b - zBefore;
        int node = g * 8 + (threadIdx.x >> 5);
        if (node < N_NODES) decf_body_warp(node);
    }
}

// ---------------- final: out = sf^2 + (1-sf)*sigmoid(z2c0[r]+z2c0[c]); reset state ----------------
__global__ __launch_bounds__(256) void final_kernel(float* __restrict__ out) {
    int e = blockIdx.x * blockDim.x + threadIdx.x;
    if (e < N_NODES) { g_cnt[e] = 0; g_pos[e] = 0; }
    if (e == 0) ct_cvt = 0;
    if (e >= N_EDGES) return;
    float sf = g_sf[e];
    float vn = g_z2c0[g_src[e]] + g_z2c0[g_tgt[e]];
    float sn = 1.f / (1.f + __expf(-vn));
    out[e] = sf * sf + (1.f - sf) * sn;
}

// ---------------- launch ----------------
extern "C" void kernel_launch(void* const* d_in, const int* in_sizes, int n_in,
                              void* d_out, int out_size) {
    const float* x    = (const float*)d_in[0];
    const float* x2   = (const float*)d_in[1];
    const float* W2   = (const float*)d_in[2];
    const float* b2   = (const float*)d_in[3];
    const float* Wg   = (const float*)d_in[4];
    const float* bg   = (const float*)d_in[5];
    const float* W22  = (const float*)d_in[6];
    const int*   edge = (const int*)d_in[7];
    float* out = (float*)d_out;

    fatA_kernel<<<GEMM_BLOCKS + AUX_BLOCKS + Z2A_BLK, 256>>>(x, W2, b2, edge, x2, W22);
    fatB_kernel<<<GEMM_BLOCKS + AUX_BLOCKS + Z2B_BLK, 256>>>(Wg, x2, W22);
    fatC_kernel<<<GATHER_BLOCKS + Z2C_BLK, 256>>>(bg, x2, W22);
    fatD_kernel<<<DECF_BLOCKS + Z2D_BLK, 256>>>(x2, W22);
    final_kernel<<<(N_EDGES + 255) / 256, 256>>>(out);
}